// round 5
// baseline (speedup 1.0000x reference)
#include <cuda_runtime.h>
#include <cuda_bf16.h>
#include <math.h>
#include <stdint.h>

#define B_SZ   32
#define CH     256
#define L_SEQ  784
#define DI     512
#define DS     16
#define DCONV  4
#define DTR    16
#define MTOT   (B_SZ * L_SEQ)   // 25088

#define W_IN_OFF  0
#define W_XP_OFF  262144
#define W_OUT_OFF 286720
#define WTOT      417792

// ---------------- scratch (static __device__, no allocation) ----------------
__device__ __nv_bfloat16 g_xnh[(size_t)MTOT * CH];
__device__ __nv_bfloat16 g_xnl[(size_t)MTOT * CH];
__device__ __nv_bfloat16 g_xch[(size_t)MTOT * DI];
__device__ __nv_bfloat16 g_xcl[(size_t)MTOT * DI];
__device__ __nv_bfloat16 g_yh [(size_t)MTOT * DI];
__device__ __nv_bfloat16 g_yl [(size_t)MTOT * DI];
__device__ __nv_bfloat16 g_wh [2 * (size_t)WTOT];
__device__ __nv_bfloat16 g_wl [2 * (size_t)WTOT];
__device__ float g_xz  [(size_t)MTOT * 2 * DI];
__device__ float g_xdp [4][(size_t)MTOT * 48];
__device__ float g_xbuf[(size_t)B_SZ * CH * L_SEQ];

// ============================================================================
// helpers
// ============================================================================
__device__ __forceinline__ void cpa16(uint32_t s, const void* g) {
    asm volatile("cp.async.cg.shared.global [%0], [%1], 16;" :: "r"(s), "l"(g));
}
__device__ __forceinline__ void ldsm4(uint32_t q[4], uint32_t addr) {
    asm volatile("ldmatrix.sync.aligned.m8n8.x4.shared.b16 {%0,%1,%2,%3}, [%4];"
                 : "=r"(q[0]), "=r"(q[1]), "=r"(q[2]), "=r"(q[3]) : "r"(addr));
}
__device__ __forceinline__ void mma_bf16(float* c, const uint32_t a[4],
                                         uint32_t b0, uint32_t b1) {
    asm volatile("mma.sync.aligned.m16n8k16.row.col.f32.bf16.bf16.f32 "
                 "{%0,%1,%2,%3},{%4,%5,%6,%7},{%8,%9},{%0,%1,%2,%3};"
                 : "+f"(c[0]), "+f"(c[1]), "+f"(c[2]), "+f"(c[3])
                 : "r"(a[0]), "r"(a[1]), "r"(a[2]), "r"(a[3]), "r"(b0), "r"(b1));
}
__device__ __forceinline__ void splitf(float x, __nv_bfloat16& h, __nv_bfloat16& l) {
    h = __float2bfloat16(x);
    l = __float2bfloat16(x - __bfloat162float(h));
}

// ---------------- elementwise f32 -> (hi, lo) bf16 split ----------------------
__global__ void split_kernel(const float* __restrict__ src,
                             __nv_bfloat16* __restrict__ hi,
                             __nv_bfloat16* __restrict__ lo, int n) {
    int i = blockIdx.x * 256 + threadIdx.x;
    if (i < n) {
        __nv_bfloat16 h, l;
        splitf(src[i], h, l);
        hi[i] = h; lo[i] = l;
    }
}

// ============================================================================
// GEMM C[M,N(+)] = A[M,K]*B[N,K]^T from pre-split bf16 planes, 3-term.
// BM=128, BN=64, BK=32, 256 thr, warps 4(m) x 2(n), warp tile 32x32.
// cp.async 3-stage ring, 1 sync/k-tile. gridDim.z = split-K factor
// (each z computes its K-chunk into C + z*M*N).
// ============================================================================
#define RSU   20                   // u32 per smem row (32 bf16 + 16B pad)
#define A_U32 (128 * RSU)
#define B_U32 (64 * RSU)
#define STAGE (2 * A_U32 + 2 * B_U32)   // 7680 u32 = 30720 B
#define GSMEM (3 * STAGE * 4)           // 92160 B

template<int TRANS>
__global__ void __launch_bounds__(256)
gemm_sp(const __nv_bfloat16* __restrict__ Ah, const __nv_bfloat16* __restrict__ Al,
        const __nv_bfloat16* __restrict__ Bh, const __nv_bfloat16* __restrict__ Bl,
        float* __restrict__ C, int M, int N, int K) {
    extern __shared__ uint32_t smu[];
    const uint32_t sb0 = (uint32_t)__cvta_generic_to_shared(smu);

    const int tid  = threadIdx.x;
    const int bm   = blockIdx.y * 128;
    const int bn   = blockIdx.x * 64;
    const int Kloc = K / gridDim.z;
    const int koff = blockIdx.z * Kloc;
    C += (size_t)blockIdx.z * M * N;

    const int warp = tid >> 5, lane = tid & 31;
    const int wm = warp >> 1, wn = warp & 1;
    const int lm = lane >> 3, lr = lane & 7;
    const int r  = lane >> 2, cc = lane & 3;

    // producer coords
    const int arow = tid >> 1, aq0 = (tid & 1) * 2;   // A: 2 chunks/thread
    const int brow = tid >> 2, bq  = tid & 3;         // B: 1 chunk/thread
    const int brn  = min(bn + brow, N - 1);

    float acc[2][4][4];
    #pragma unroll
    for (int i = 0; i < 2; i++)
        #pragma unroll
        for (int j = 0; j < 4; j++)
            #pragma unroll
            for (int v = 0; v < 4; v++) acc[i][j][v] = 0.0f;

    const int KT = Kloc >> 5;

    auto load_tile = [&](int stage, int kt) {
        const int k0 = koff + (kt << 5);
        const uint32_t sb = sb0 + (uint32_t)(stage * STAGE) * 4;
        #pragma unroll
        for (int j = 0; j < 2; j++) {
            int q = aq0 + j;
            size_t go = (size_t)(bm + arow) * K + k0 + q * 8;
            uint32_t so = sb + (uint32_t)(arow * RSU + q * 4) * 4;
            cpa16(so, Ah + go);
            cpa16(so + A_U32 * 4, Al + go);
        }
        {
            size_t go = (size_t)brn * K + k0 + bq * 8;
            uint32_t so = sb + (uint32_t)(2 * A_U32 + brow * RSU + bq * 4) * 4;
            cpa16(so, Bh + go);
            cpa16(so + B_U32 * 4, Bl + go);
        }
        asm volatile("cp.async.commit_group;");
    };

    load_tile(0, 0);
    if (KT > 1) load_tile(1, 1);

    for (int kt = 0; kt < KT; kt++) {
        if (kt + 1 < KT) asm volatile("cp.async.wait_group 1;");
        else             asm volatile("cp.async.wait_group 0;");
        __syncthreads();
        if (kt + 2 < KT) load_tile((kt + 2) % 3, kt + 2);

        const uint32_t stb = sb0 + (uint32_t)((kt % 3) * STAGE) * 4;
        #pragma unroll
        for (int ks = 0; ks < 2; ks++) {
            uint32_t BH[4][2], BL[4][2];
            #pragma unroll
            for (int tt = 0; tt < 2; tt++) {
                uint32_t rowb = wn * 32 + tt * 16 + (lm & 1) * 8 + lr;
                uint32_t ad = stb + (2 * A_U32) * 4 + rowb * 80 + ks * 32 + (lm >> 1) * 16;
                uint32_t q[4];
                ldsm4(q, ad);
                BH[2*tt][0] = q[0]; BH[2*tt+1][0] = q[1];
                BH[2*tt][1] = q[2]; BH[2*tt+1][1] = q[3];
                ldsm4(q, ad + B_U32 * 4);
                BL[2*tt][0] = q[0]; BL[2*tt+1][0] = q[1];
                BL[2*tt][1] = q[2]; BL[2*tt+1][1] = q[3];
            }
            #pragma unroll
            for (int mi = 0; mi < 2; mi++) {
                uint32_t rowa = wm * 32 + mi * 16 + (lm & 1) * 8 + lr;
                uint32_t ad = stb + rowa * 80 + ks * 32 + (lm >> 1) * 16;
                uint32_t AH[4], AL[4];
                ldsm4(AH, ad);
                ldsm4(AL, ad + A_U32 * 4);
                #pragma unroll
                for (int ni = 0; ni < 4; ni++) {
                    mma_bf16(acc[mi][ni], AH, BH[ni][0], BH[ni][1]);
                    mma_bf16(acc[mi][ni], AL, BH[ni][0], BH[ni][1]);
                    mma_bf16(acc[mi][ni], AH, BL[ni][0], BL[ni][1]);
                }
            }
        }
    }

    if (!TRANS) {
        #pragma unroll
        for (int mi = 0; mi < 2; mi++) {
            int row0 = bm + wm * 32 + mi * 16 + r;
            #pragma unroll
            for (int ni = 0; ni < 4; ni++) {
                int col = bn + wn * 32 + ni * 8 + 2 * cc;
                if (col < N) {
                    *reinterpret_cast<float2*>(C + (size_t)row0 * N + col) =
                        make_float2(acc[mi][ni][0], acc[mi][ni][1]);
                    *reinterpret_cast<float2*>(C + (size_t)(row0 + 8) * N + col) =
                        make_float2(acc[mi][ni][2], acc[mi][ni][3]);
                }
            }
        }
    } else {
        float* ct = reinterpret_cast<float*>(smu);   // [64][132]
        __syncthreads();
        #pragma unroll
        for (int mi = 0; mi < 2; mi++) {
            int m0 = wm * 32 + mi * 16 + r;
            #pragma unroll
            for (int ni = 0; ni < 4; ni++) {
                int n0 = wn * 32 + ni * 8 + 2 * cc;
                ct[(n0    ) * 132 + m0    ] = acc[mi][ni][0];
                ct[(n0 + 1) * 132 + m0    ] = acc[mi][ni][1];
                ct[(n0    ) * 132 + m0 + 8] = acc[mi][ni][2];
                ct[(n0 + 1) * 132 + m0 + 8] = acc[mi][ni][3];
            }
        }
        __syncthreads();
        for (int i = tid; i < 64 * 128; i += 256) {
            int n = i >> 7, m = i & 127;
            int row = bm + m;
            int b = row / L_SEQ;
            int l = row - b * L_SEQ;
            C[((size_t)b * N + bn + n) * L_SEQ + l] = ct[n * 132 + m];
        }
    }
}

// ---------------- LayerNorm -> split bf16 planes (B,C,L)->(B*L,C) -------------
__global__ void ln_kernel(const float* __restrict__ x,
                          const float* __restrict__ w,
                          const float* __restrict__ bb,
                          __nv_bfloat16* __restrict__ oh,
                          __nv_bfloat16* __restrict__ ol) {
    __shared__ float s[256][17];
    int l0 = blockIdx.x * 16;
    int b  = blockIdx.y;
    int tid = threadIdx.x;

    for (int i = tid; i < 256 * 16; i += 256) {
        int c = i >> 4, l = i & 15;
        s[c][l] = x[((size_t)b * CH + c) * L_SEQ + l0 + l];
    }
    __syncthreads();

    int l = tid >> 4, part = tid & 15;
    float a = 0.f, q = 0.f;
    #pragma unroll
    for (int j = 0; j < 16; j++) {
        float v = s[part + 16 * j][l];
        a += v;
        q = fmaf(v, v, q);
    }
    #pragma unroll
    for (int o = 1; o < 16; o <<= 1) {
        a += __shfl_xor_sync(0xffffffffu, a, o);
        q += __shfl_xor_sync(0xffffffffu, q, o);
    }
    float mu  = a * (1.0f / CH);
    float var = q * (1.0f / CH) - mu * mu;
    float inv = rsqrtf(var + 1e-5f);

    size_t base = (size_t)(b * L_SEQ + l0 + l) * CH;
    #pragma unroll
    for (int j = 0; j < 16; j++) {
        int c = part + 16 * j;
        float v = (s[c][l] - mu) * inv * w[c] + bb[c];
        __nv_bfloat16 h, lo;
        splitf(v, h, lo);
        oh[base + c] = h; ol[base + c] = lo;
    }
}

// ---------------- causal conv (k=4) + SiLU -> split planes --------------------
__global__ void conv_silu_kernel(const float* __restrict__ cw,
                                 const float* __restrict__ cb) {
    int idx  = blockIdx.x * 256 + threadIdx.x;   // MTOT*DI/4
    int base = idx * 4;
    int d    = base & (DI - 1);
    int bl   = base >> 9;
    int l    = bl % L_SEQ;

    float4 acc = *reinterpret_cast<const float4*>(cb + d);
    float4 w0 = *reinterpret_cast<const float4*>(cw + (d + 0) * 4);
    float4 w1 = *reinterpret_cast<const float4*>(cw + (d + 1) * 4);
    float4 w2 = *reinterpret_cast<const float4*>(cw + (d + 2) * 4);
    float4 w3 = *reinterpret_cast<const float4*>(cw + (d + 3) * 4);
    const float wk[4][4] = {{w0.x, w1.x, w2.x, w3.x}, {w0.y, w1.y, w2.y, w3.y},
                            {w0.z, w1.z, w2.z, w3.z}, {w0.w, w1.w, w2.w, w3.w}};
    #pragma unroll
    for (int k = 0; k < DCONV; k++) {
        int ll = l - 3 + k;
        if (ll >= 0) {
            float4 v = *reinterpret_cast<const float4*>(
                g_xz + (size_t)(bl - 3 + k) * (2 * DI) + d);
            acc.x = fmaf(v.x, wk[k][0], acc.x);
            acc.y = fmaf(v.y, wk[k][1], acc.y);
            acc.z = fmaf(v.z, wk[k][2], acc.z);
            acc.w = fmaf(v.w, wk[k][3], acc.w);
        }
    }
    float o[4] = {acc.x, acc.y, acc.z, acc.w};
    __nv_bfloat16 h[4], lo[4];
    #pragma unroll
    for (int k = 0; k < 4; k++) {
        o[k] = o[k] / (1.0f + __expf(-o[k]));
        splitf(o[k], h[k], lo[k]);
    }
    *reinterpret_cast<uint2*>(g_xch + base) = *reinterpret_cast<uint2*>(h);
    *reinterpret_cast<uint2*>(g_xcl + base) = *reinterpret_cast<uint2*>(lo);
}

// ---------------- selective scan (fused dt_proj + split-K reduce) -------------
__global__ void scan_kernel(const float* __restrict__ A_log,
                            const float* __restrict__ Dp,
                            const float* __restrict__ dtw,
                            const float* __restrict__ dtb) {
    int b    = blockIdx.x;
    int tid  = threadIdx.x;                 // 128
    int dl   = tid >> 1, half = tid & 1;
    int d    = blockIdx.y * 64 + dl;

    float w[DTR];
    #pragma unroll
    for (int i = 0; i < DTR; i++) w[i] = dtw[d * DTR + i];
    float bias = dtb[d];

    float a[8];
    bool powok = true;
    #pragma unroll
    for (int s = 0; s < 8; s++) {
        a[s] = -__expf(A_log[d * DS + half * 8 + s]);
        float kf = (float)(half * 8 + s + 1);
        powok = powok && (fabsf(-a[s] - kf) < 1e-3f * kf);
    }
    float Dd = Dp[d];

    float h[8];
    #pragma unroll
    for (int s = 0; s < 8; s++) h[s] = 0.0f;

    __shared__ float sBC[16][48];

    for (int c0 = 0; c0 < L_SEQ; c0 += 16) {
        __syncthreads();
        for (int i = tid; i < 16 * 48; i += 128) {
            int st = i / 48, j = i - st * 48;
            size_t ro = ((size_t)b * L_SEQ + c0 + st) * 48 + j;
            sBC[st][j] = (g_xdp[0][ro] + g_xdp[1][ro]) + (g_xdp[2][ro] + g_xdp[3][ro]);
        }
        __syncthreads();
        #pragma unroll 4
        for (int st = 0; st < 16; st++) {
            size_t row = (size_t)b * L_SEQ + c0 + st;
            float dtl = bias;
            #pragma unroll
            for (int i = 0; i < DTR; i++) dtl = fmaf(w[i], sBC[st][i], dtl);
            float dtv = (dtl > 20.0f) ? dtl : log1pf(__expf(dtl));
            float xv  = __bfloat162float(g_xch[row * DI + d]) +
                        __bfloat162float(g_xcl[row * DI + d]);
            float dtx = dtv * xv;
            float dA[8];
            if (powok) {
                float rr = __expf(-dtv);
                float r2 = rr * rr, r4 = r2 * r2, r8v = r4 * r4;
                float p = half ? r8v : 1.0f;
                #pragma unroll
                for (int s = 0; s < 8; s++) { p *= rr; dA[s] = p; }
            } else {
                #pragma unroll
                for (int s = 0; s < 8; s++) dA[s] = __expf(dtv * a[s]);
            }
            float yacc = 0.0f;
            #pragma unroll
            for (int s = 0; s < 8; s++) {
                h[s] = fmaf(h[s], dA[s], dtx * sBC[st][16 + half * 8 + s]);
                yacc = fmaf(h[s], sBC[st][32 + half * 8 + s], yacc);
            }
            yacc += __shfl_xor_sync(0xffffffffu, yacc, 1);
            if (half == 0) {
                float zv = g_xz[row * 2 * DI + DI + d];
                float yf = fmaf(xv, Dd, yacc) * (zv / (1.0f + __expf(-zv)));
                __nv_bfloat16 hh, ll;
                splitf(yf, hh, ll);
                g_yh[row * DI + d] = hh;
                g_yl[row * DI + d] = ll;
            }
        }
    }
}

// ------------------------------- launcher -------------------------------------
extern "C" void kernel_launch(void* const* d_in, const int* in_sizes, int n_in,
                              void* d_out, int out_size) {
    const float* bbox   = (const float*)d_in[0];
    const float* norm_w = (const float*)d_in[1];
    const float* norm_b = (const float*)d_in[2];
    const float* in_w   = (const float*)d_in[3];
    const float* conv_w = (const float*)d_in[4];
    const float* conv_b = (const float*)d_in[5];
    const float* xp_w   = (const float*)d_in[6];
    const float* dtp_w  = (const float*)d_in[7];
    const float* dtp_b  = (const float*)d_in[8];
    const float* A_log  = (const float*)d_in[9];
    const float* Dp     = (const float*)d_in[10];
    const float* out_w  = (const float*)d_in[11];
    float* out = (float*)d_out;

    cudaFuncSetAttribute(gemm_sp<0>, cudaFuncAttributeMaxDynamicSharedMemorySize, GSMEM);
    cudaFuncSetAttribute(gemm_sp<1>, cudaFuncAttributeMaxDynamicSharedMemorySize, GSMEM);

    __nv_bfloat16 *xnh, *xnl, *xch, *xcl, *yh, *yl, *wh, *wl;
    float *xz, *xdp, *xbuf;
    cudaGetSymbolAddress((void**)&xnh, g_xnh);
    cudaGetSymbolAddress((void**)&xnl, g_xnl);
    cudaGetSymbolAddress((void**)&xch, g_xch);
    cudaGetSymbolAddress((void**)&xcl, g_xcl);
    cudaGetSymbolAddress((void**)&yh,  g_yh);
    cudaGetSymbolAddress((void**)&yl,  g_yl);
    cudaGetSymbolAddress((void**)&wh,  g_wh);
    cudaGetSymbolAddress((void**)&wl,  g_wl);
    cudaGetSymbolAddress((void**)&xz,  g_xz);
    cudaGetSymbolAddress((void**)&xdp, g_xdp);
    cudaGetSymbolAddress((void**)&xbuf, g_xbuf);

    // ---- split weights (both depths) ----
    for (int i = 0; i < 2; i++) {
        size_t wb = (size_t)i * WTOT;
        split_kernel<<<(2 * DI * CH + 255) / 256, 256>>>(
            in_w + (size_t)i * 2 * DI * CH, wh + wb + W_IN_OFF, wl + wb + W_IN_OFF, 2 * DI * CH);
        split_kernel<<<(48 * DI + 255) / 256, 256>>>(
            xp_w + (size_t)i * 48 * DI, wh + wb + W_XP_OFF, wl + wb + W_XP_OFF, 48 * DI);
        split_kernel<<<(CH * DI + 255) / 256, 256>>>(
            out_w + (size_t)i * CH * DI, wh + wb + W_OUT_OFF, wl + wb + W_OUT_OFF, CH * DI);
    }

    for (int i = 0; i < 2; i++) {
        const float* xin = (i == 0) ? bbox : xbuf;
        float* xout      = (i == 0) ? xbuf : out;
        size_t wb = (size_t)i * WTOT;

        {   // layernorm -> split planes
            dim3 g(49, 32);
            ln_kernel<<<g, 256>>>(xin, norm_w + i * CH, norm_b + i * CH, xnh, xnl);
        }
        {   // in_proj: (25088,256)x(1024,256)^T -> f32 xz
            dim3 g(1024 / 64, MTOT / 128, 1);
            gemm_sp<0><<<g, 256, GSMEM>>>(xnh, xnl, wh + wb + W_IN_OFF, wl + wb + W_IN_OFF,
                                          xz, MTOT, 2 * DI, CH);
        }
        // conv + silu -> split planes
        conv_silu_kernel<<<(MTOT * DI / 4) / 256, 256>>>(conv_w + i * DI * DCONV,
                                                         conv_b + i * DI);
        {   // x_proj: split-K=4 -> 4 partial (25088,48) buffers
            dim3 g(1, MTOT / 128, 4);
            gemm_sp<0><<<g, 256, GSMEM>>>(xch, xcl, wh + wb + W_XP_OFF, wl + wb + W_XP_OFF,
                                          xdp, MTOT, 48, DI);
        }
        {   // selective scan (fused dt_proj, sums partials) -> split y planes
            dim3 g(B_SZ, DI / 64);
            scan_kernel<<<g, 128>>>(A_log + i * DI * DS, Dp + i * DI,
                                    dtp_w + (size_t)i * DI * DTR, dtp_b + i * DI);
        }
        {   // out_proj: (25088,512)x(256,512)^T -> (B,256,L)
            dim3 g(256 / 64, MTOT / 128, 1);
            gemm_sp<1><<<g, 256, GSMEM>>>(yh, yl, wh + wb + W_OUT_OFF, wl + wb + W_OUT_OFF,
                                          xout, MTOT, CH, DI);
        }
    }
}

// round 6
// speedup vs baseline: 1.0356x; 1.0356x over previous
#include <cuda_runtime.h>
#include <cuda_bf16.h>
#include <math.h>
#include <stdint.h>

#define B_SZ   32
#define CH     256
#define L_SEQ  784
#define DI     512
#define DS     16
#define DCONV  4
#define DTR    16
#define MTOT   (B_SZ * L_SEQ)   // 25088

#define W_IN_OFF  0
#define W_XP_OFF  262144
#define W_OUT_OFF 286720
#define WTOT      417792

// ---------------- scratch (static __device__, no allocation) ----------------
__device__ __nv_bfloat16 g_xnh[(size_t)MTOT * CH];
__device__ __nv_bfloat16 g_xnl[(size_t)MTOT * CH];
__device__ __nv_bfloat16 g_xch[(size_t)MTOT * DI];
__device__ __nv_bfloat16 g_xcl[(size_t)MTOT * DI];
__device__ __nv_bfloat16 g_yh [(size_t)MTOT * DI];
__device__ __nv_bfloat16 g_yl [(size_t)MTOT * DI];
__device__ __nv_bfloat16 g_wh [2 * (size_t)WTOT];
__device__ __nv_bfloat16 g_wl [2 * (size_t)WTOT];
__device__ float g_xz  [(size_t)MTOT * 2 * DI];
__device__ float g_xdp [4][(size_t)MTOT * 48];
__device__ float g_xbuf[(size_t)B_SZ * CH * L_SEQ];

// ============================================================================
// helpers
// ============================================================================
__device__ __forceinline__ void cpa16(uint32_t s, const void* g) {
    asm volatile("cp.async.cg.shared.global [%0], [%1], 16;" :: "r"(s), "l"(g));
}
__device__ __forceinline__ void ldsm4(uint32_t q[4], uint32_t addr) {
    asm volatile("ldmatrix.sync.aligned.m8n8.x4.shared.b16 {%0,%1,%2,%3}, [%4];"
                 : "=r"(q[0]), "=r"(q[1]), "=r"(q[2]), "=r"(q[3]) : "r"(addr));
}
__device__ __forceinline__ void mma_bf16(float* c, const uint32_t a[4],
                                         uint32_t b0, uint32_t b1) {
    asm volatile("mma.sync.aligned.m16n8k16.row.col.f32.bf16.bf16.f32 "
                 "{%0,%1,%2,%3},{%4,%5,%6,%7},{%8,%9},{%0,%1,%2,%3};"
                 : "+f"(c[0]), "+f"(c[1]), "+f"(c[2]), "+f"(c[3])
                 : "r"(a[0]), "r"(a[1]), "r"(a[2]), "r"(a[3]), "r"(b0), "r"(b1));
}
__device__ __forceinline__ void splitf(float x, __nv_bfloat16& h, __nv_bfloat16& l) {
    h = __float2bfloat16(x);
    l = __float2bfloat16(x - __bfloat162float(h));
}
// swizzled byte offset within a plane: row has 4 chunks of 16B (64B/row)
__device__ __forceinline__ uint32_t swoff(int row, int c) {
    return (uint32_t)(row * 64 + ((c ^ ((row >> 1) & 3)) << 4));
}

// ---------------- fused weight split (one launch, both depths) ---------------
__global__ void split_w_kernel(const float* __restrict__ in_w,
                               const float* __restrict__ xp_w,
                               const float* __restrict__ out_w,
                               __nv_bfloat16* __restrict__ wh,
                               __nv_bfloat16* __restrict__ wl) {
    int i = blockIdx.x * 256 + threadIdx.x;
    if (i >= 2 * WTOT) return;
    int depth = i / WTOT, r = i - depth * WTOT;
    float v;
    if (r < W_XP_OFF)       v = in_w [(size_t)depth * 262144 + r];
    else if (r < W_OUT_OFF) v = xp_w [(size_t)depth * 24576  + (r - W_XP_OFF)];
    else                    v = out_w[(size_t)depth * 131072 + (r - W_OUT_OFF)];
    __nv_bfloat16 h, l;
    splitf(v, h, l);
    wh[i] = h; wl[i] = l;
}

// ============================================================================
// GEMM C[M,N] = A[M,K]*B[N,K]^T from pre-split bf16 planes, 3-term bf16 mma.
// BM=128, BN=NI*32, BK=32, 256 thr, warps 2(m) x 4(n), warp tile 64x(NI*8).
// cp.async 3-stage ring, swizzled 64B rows, 1 sync per k-tile.
// gridDim.z = split-K factor; z writes C + z*M*N.
// ============================================================================
template<int NI, int TRANS>
__global__ void __launch_bounds__(256, 2)
gemm_cp(const __nv_bfloat16* __restrict__ Ah, const __nv_bfloat16* __restrict__ Al,
        const __nv_bfloat16* __restrict__ Bh, const __nv_bfloat16* __restrict__ Bl,
        float* __restrict__ C, int M, int N, int K) {
    constexpr int BROWS   = NI * 32;
    constexpr int A_BYTES = 128 * 64;
    constexpr int B_BYTES = BROWS * 64;
    constexpr int STAGEB  = 2 * A_BYTES + 2 * B_BYTES;

    extern __shared__ uint8_t smb[];
    const uint32_t sb0 = (uint32_t)__cvta_generic_to_shared(smb);

    const int tid  = threadIdx.x;
    const int bm   = blockIdx.y * 128;
    const int bn   = blockIdx.x * BROWS;
    const int Kloc = K / gridDim.z;
    const int koff = blockIdx.z * Kloc;
    C += (size_t)blockIdx.z * M * N;

    const int warp = tid >> 5, lane = tid & 31;
    const int wm = warp & 1, wn = warp >> 1;
    const int lm = lane >> 3, lr = lane & 7;
    const int r  = lane >> 2, cc = lane & 3;

    float acc[4][NI][4];
    #pragma unroll
    for (int i = 0; i < 4; i++)
        #pragma unroll
        for (int j = 0; j < NI; j++)
            #pragma unroll
            for (int v = 0; v < 4; v++) acc[i][j][v] = 0.0f;

    const int KT = Kloc >> 5;

    const int prow = tid >> 1;               // A (and B when NI==4)
    const int pc0  = (tid & 1) * 2;
    const int br2  = tid >> 2, bc2 = tid & 3;   // B when NI==2
    const int brnA = (NI == 4) ? min(bn + prow, N - 1) : 0;
    const int brnB = (NI == 2) ? min(bn + br2, N - 1) : 0;

    auto load_tile = [&](int stage, int kt) {
        const int k0 = koff + (kt << 5);
        const uint32_t sb = sb0 + (uint32_t)stage * STAGEB;
        #pragma unroll
        for (int j = 0; j < 2; j++) {
            int c = pc0 + j;
            size_t go = (size_t)(bm + prow) * K + k0 + c * 8;
            uint32_t so = sb + swoff(prow, c);
            cpa16(so, Ah + go);
            cpa16(so + A_BYTES, Al + go);
        }
        if (NI == 4) {
            #pragma unroll
            for (int j = 0; j < 2; j++) {
                int c = pc0 + j;
                size_t go = (size_t)brnA * K + k0 + c * 8;
                uint32_t so = sb + 2 * A_BYTES + swoff(prow, c);
                cpa16(so, Bh + go);
                cpa16(so + B_BYTES, Bl + go);
            }
        } else {
            size_t go = (size_t)brnB * K + k0 + bc2 * 8;
            uint32_t so = sb + 2 * A_BYTES + swoff(br2, bc2);
            cpa16(so, Bh + go);
            cpa16(so + B_BYTES, Bl + go);
        }
        asm volatile("cp.async.commit_group;");
    };

    load_tile(0, 0);
    if (KT > 1) load_tile(1, 1);

    for (int kt = 0; kt < KT; kt++) {
        if (kt + 2 < KT) asm volatile("cp.async.wait_group 1;");
        else             asm volatile("cp.async.wait_group 0;");
        __syncthreads();
        if (kt + 2 < KT) load_tile((kt + 2) % 3, kt + 2);

        const uint32_t stb = sb0 + (uint32_t)((kt % 3)) * STAGEB;
        #pragma unroll
        for (int ks = 0; ks < 2; ks++) {
            const int chunk = ks * 2 + (lm >> 1);
            uint32_t BH[NI][2], BL[NI][2];
            #pragma unroll
            for (int tt = 0; tt < NI / 2; tt++) {
                int rowb = wn * (NI * 8) + tt * 16 + (lm & 1) * 8 + lr;
                uint32_t ad = stb + 2 * A_BYTES + swoff(rowb, chunk);
                uint32_t q[4];
                ldsm4(q, ad);
                BH[2*tt][0] = q[0]; BH[2*tt+1][0] = q[1];
                BH[2*tt][1] = q[2]; BH[2*tt+1][1] = q[3];
                ldsm4(q, ad + B_BYTES);
                BL[2*tt][0] = q[0]; BL[2*tt+1][0] = q[1];
                BL[2*tt][1] = q[2]; BL[2*tt+1][1] = q[3];
            }
            #pragma unroll
            for (int mi = 0; mi < 4; mi++) {
                int rowa = wm * 64 + mi * 16 + (lm & 1) * 8 + lr;
                uint32_t ad = stb + swoff(rowa, chunk);
                uint32_t AH[4], AL[4];
                ldsm4(AH, ad);
                ldsm4(AL, ad + A_BYTES);
                #pragma unroll
                for (int ni = 0; ni < NI; ni++) {
                    mma_bf16(acc[mi][ni], AH, BH[ni][0], BH[ni][1]);
                    mma_bf16(acc[mi][ni], AL, BH[ni][0], BH[ni][1]);
                    mma_bf16(acc[mi][ni], AH, BL[ni][0], BL[ni][1]);
                }
            }
        }
    }

    if (!TRANS) {
        #pragma unroll
        for (int mi = 0; mi < 4; mi++) {
            int row0 = bm + wm * 64 + mi * 16 + r;
            #pragma unroll
            for (int ni = 0; ni < NI; ni++) {
                int col = bn + wn * (NI * 8) + ni * 8 + 2 * cc;
                if (col < N) {
                    *reinterpret_cast<float2*>(C + (size_t)row0 * N + col) =
                        make_float2(acc[mi][ni][0], acc[mi][ni][1]);
                    *reinterpret_cast<float2*>(C + (size_t)(row0 + 8) * N + col) =
                        make_float2(acc[mi][ni][2], acc[mi][ni][3]);
                }
            }
        }
    } else {
        // NI==4: transpose 64 n-cols at a time -> coalesced (B,N,L)
        float* ct = reinterpret_cast<float*>(smb);
        __syncthreads();
        #pragma unroll
        for (int half = 0; half < 2; half++) {
            if ((wn >> 1) == half) {
                #pragma unroll
                for (int mi = 0; mi < 4; mi++) {
                    int m0 = wm * 64 + mi * 16 + r;
                    #pragma unroll
                    for (int ni = 0; ni < NI; ni++) {
                        int n0 = (wn - half * 2) * 32 + ni * 8 + 2 * cc;
                        ct[(n0    ) * 132 + m0    ] = acc[mi][ni][0];
                        ct[(n0 + 1) * 132 + m0    ] = acc[mi][ni][1];
                        ct[(n0    ) * 132 + m0 + 8] = acc[mi][ni][2];
                        ct[(n0 + 1) * 132 + m0 + 8] = acc[mi][ni][3];
                    }
                }
            }
            __syncthreads();
            for (int i = tid; i < 64 * 128; i += 256) {
                int n = i >> 7, m = i & 127;
                int row = bm + m;
                int b = row / L_SEQ;
                int l = row - b * L_SEQ;
                C[((size_t)b * N + bn + half * 64 + n) * L_SEQ + l] = ct[n * 132 + m];
            }
            __syncthreads();
        }
    }
}

// ---------------- LayerNorm -> split bf16 planes (B,C,L)->(B*L,C) -------------
__global__ void ln_kernel(const float* __restrict__ x,
                          const float* __restrict__ w,
                          const float* __restrict__ bb,
                          __nv_bfloat16* __restrict__ oh,
                          __nv_bfloat16* __restrict__ ol) {
    __shared__ float s[256][17];
    int l0 = blockIdx.x * 16;
    int b  = blockIdx.y;
    int tid = threadIdx.x;

    for (int i = tid; i < 256 * 16; i += 256) {
        int c = i >> 4, l = i & 15;
        s[c][l] = x[((size_t)b * CH + c) * L_SEQ + l0 + l];
    }
    __syncthreads();

    int l = tid >> 4, part = tid & 15;
    float a = 0.f, q = 0.f;
    #pragma unroll
    for (int j = 0; j < 16; j++) {
        float v = s[part + 16 * j][l];
        a += v;
        q = fmaf(v, v, q);
    }
    #pragma unroll
    for (int o = 1; o < 16; o <<= 1) {
        a += __shfl_xor_sync(0xffffffffu, a, o);
        q += __shfl_xor_sync(0xffffffffu, q, o);
    }
    float mu  = a * (1.0f / CH);
    float var = q * (1.0f / CH) - mu * mu;
    float inv = rsqrtf(var + 1e-5f);

    size_t base = (size_t)(b * L_SEQ + l0 + l) * CH;
    #pragma unroll
    for (int j = 0; j < 16; j++) {
        int c = part + 16 * j;
        float v = (s[c][l] - mu) * inv * w[c] + bb[c];
        __nv_bfloat16 h, lo;
        splitf(v, h, lo);
        oh[base + c] = h; ol[base + c] = lo;
    }
}

// ---------------- causal conv (k=4) + SiLU -> split planes --------------------
__global__ void conv_silu_kernel(const float* __restrict__ cw,
                                 const float* __restrict__ cb) {
    int idx  = blockIdx.x * 256 + threadIdx.x;   // MTOT*DI/4
    int base = idx * 4;
    int d    = base & (DI - 1);
    int bl   = base >> 9;
    int l    = bl % L_SEQ;

    float4 acc = *reinterpret_cast<const float4*>(cb + d);
    float4 w0 = *reinterpret_cast<const float4*>(cw + (d + 0) * 4);
    float4 w1 = *reinterpret_cast<const float4*>(cw + (d + 1) * 4);
    float4 w2 = *reinterpret_cast<const float4*>(cw + (d + 2) * 4);
    float4 w3 = *reinterpret_cast<const float4*>(cw + (d + 3) * 4);
    const float wk[4][4] = {{w0.x, w1.x, w2.x, w3.x}, {w0.y, w1.y, w2.y, w3.y},
                            {w0.z, w1.z, w2.z, w3.z}, {w0.w, w1.w, w2.w, w3.w}};
    #pragma unroll
    for (int k = 0; k < DCONV; k++) {
        int ll = l - 3 + k;
        if (ll >= 0) {
            float4 v = *reinterpret_cast<const float4*>(
                g_xz + (size_t)(bl - 3 + k) * (2 * DI) + d);
            acc.x = fmaf(v.x, wk[k][0], acc.x);
            acc.y = fmaf(v.y, wk[k][1], acc.y);
            acc.z = fmaf(v.z, wk[k][2], acc.z);
            acc.w = fmaf(v.w, wk[k][3], acc.w);
        }
    }
    float o[4] = {acc.x, acc.y, acc.z, acc.w};
    __nv_bfloat16 h[4], lo[4];
    #pragma unroll
    for (int k = 0; k < 4; k++) {
        o[k] = o[k] / (1.0f + __expf(-o[k]));
        splitf(o[k], h[k], lo[k]);
    }
    *reinterpret_cast<uint2*>(g_xch + base) = *reinterpret_cast<uint2*>(h);
    *reinterpret_cast<uint2*>(g_xcl + base) = *reinterpret_cast<uint2*>(lo);
}

// ---------------- selective scan (fused dt_proj + split-K reduce) -------------
__global__ void scan_kernel(const float* __restrict__ A_log,
                            const float* __restrict__ Dp,
                            const float* __restrict__ dtw,
                            const float* __restrict__ dtb) {
    int b    = blockIdx.x;
    int tid  = threadIdx.x;                 // 128
    int dl   = tid >> 1, half = tid & 1;
    int d    = blockIdx.y * 64 + dl;

    float w[DTR];
    #pragma unroll
    for (int i = 0; i < DTR; i++) w[i] = dtw[d * DTR + i];
    float bias = dtb[d];

    float a[8];
    bool powok = true;
    #pragma unroll
    for (int s = 0; s < 8; s++) {
        a[s] = -__expf(A_log[d * DS + half * 8 + s]);
        float kf = (float)(half * 8 + s + 1);
        powok = powok && (fabsf(-a[s] - kf) < 1e-3f * kf);
    }
    float Dd = Dp[d];

    float h[8];
    #pragma unroll
    for (int s = 0; s < 8; s++) h[s] = 0.0f;

    __shared__ float sBC[16][48];

    for (int c0 = 0; c0 < L_SEQ; c0 += 16) {
        __syncthreads();
        for (int i = tid; i < 16 * 48; i += 128) {
            int st = i / 48, j = i - st * 48;
            size_t ro = ((size_t)b * L_SEQ + c0 + st) * 48 + j;
            sBC[st][j] = (g_xdp[0][ro] + g_xdp[1][ro]) + (g_xdp[2][ro] + g_xdp[3][ro]);
        }
        __syncthreads();
        #pragma unroll 4
        for (int st = 0; st < 16; st++) {
            size_t row = (size_t)b * L_SEQ + c0 + st;
            float dtl = bias;
            #pragma unroll
            for (int i = 0; i < DTR; i++) dtl = fmaf(w[i], sBC[st][i], dtl);
            float dtv = (dtl > 20.0f) ? dtl : log1pf(__expf(dtl));
            float xv  = __bfloat162float(g_xch[row * DI + d]) +
                        __bfloat162float(g_xcl[row * DI + d]);
            float dtx = dtv * xv;
            float dA[8];
            if (powok) {
                float rr = __expf(-dtv);
                float r2 = rr * rr, r4 = r2 * r2, r8v = r4 * r4;
                float p = half ? r8v : 1.0f;
                #pragma unroll
                for (int s = 0; s < 8; s++) { p *= rr; dA[s] = p; }
            } else {
                #pragma unroll
                for (int s = 0; s < 8; s++) dA[s] = __expf(dtv * a[s]);
            }
            float yacc = 0.0f;
            #pragma unroll
            for (int s = 0; s < 8; s++) {
                h[s] = fmaf(h[s], dA[s], dtx * sBC[st][16 + half * 8 + s]);
                yacc = fmaf(h[s], sBC[st][32 + half * 8 + s], yacc);
            }
            yacc += __shfl_xor_sync(0xffffffffu, yacc, 1);
            if (half == 0) {
                float zv = g_xz[row * 2 * DI + DI + d];
                float yf = fmaf(xv, Dd, yacc) * (zv / (1.0f + __expf(-zv)));
                __nv_bfloat16 hh, ll;
                splitf(yf, hh, ll);
                g_yh[row * DI + d] = hh;
                g_yl[row * DI + d] = ll;
            }
        }
    }
}

// ------------------------------- launcher -------------------------------------
#define SMEM_NI4 (3 * (2 * 128 * 64 + 2 * 128 * 64))   // 98304
#define SMEM_NI2 (3 * (2 * 128 * 64 + 2 * 64 * 64))    // 73728

extern "C" void kernel_launch(void* const* d_in, const int* in_sizes, int n_in,
                              void* d_out, int out_size) {
    const float* bbox   = (const float*)d_in[0];
    const float* norm_w = (const float*)d_in[1];
    const float* norm_b = (const float*)d_in[2];
    const float* in_w   = (const float*)d_in[3];
    const float* conv_w = (const float*)d_in[4];
    const float* conv_b = (const float*)d_in[5];
    const float* xp_w   = (const float*)d_in[6];
    const float* dtp_w  = (const float*)d_in[7];
    const float* dtp_b  = (const float*)d_in[8];
    const float* A_log  = (const float*)d_in[9];
    const float* Dp     = (const float*)d_in[10];
    const float* out_w  = (const float*)d_in[11];
    float* out = (float*)d_out;

    cudaFuncSetAttribute(gemm_cp<4,0>, cudaFuncAttributeMaxDynamicSharedMemorySize, SMEM_NI4);
    cudaFuncSetAttribute(gemm_cp<4,1>, cudaFuncAttributeMaxDynamicSharedMemorySize, SMEM_NI4);
    cudaFuncSetAttribute(gemm_cp<2,0>, cudaFuncAttributeMaxDynamicSharedMemorySize, SMEM_NI2);

    __nv_bfloat16 *xnh, *xnl, *xch, *xcl, *yh, *yl, *wh, *wl;
    float *xz, *xbuf;
    cudaGetSymbolAddress((void**)&xnh, g_xnh);
    cudaGetSymbolAddress((void**)&xnl, g_xnl);
    cudaGetSymbolAddress((void**)&xch, g_xch);
    cudaGetSymbolAddress((void**)&xcl, g_xcl);
    cudaGetSymbolAddress((void**)&yh,  g_yh);
    cudaGetSymbolAddress((void**)&yl,  g_yl);
    cudaGetSymbolAddress((void**)&wh,  g_wh);
    cudaGetSymbolAddress((void**)&wl,  g_wl);
    cudaGetSymbolAddress((void**)&xz,  g_xz);
    cudaGetSymbolAddress((void**)&xbuf, g_xbuf);
    float* xdp;
    cudaGetSymbolAddress((void**)&xdp, g_xdp);

    // one launch: split all weights, both depths
    split_w_kernel<<<(2 * WTOT + 255) / 256, 256>>>(in_w, xp_w, out_w, wh, wl);

    for (int i = 0; i < 2; i++) {
        const float* xin = (i == 0) ? bbox : xbuf;
        float* xout      = (i == 0) ? xbuf : out;
        size_t wb = (size_t)i * WTOT;

        {   // layernorm -> split planes
            dim3 g(49, 32);
            ln_kernel<<<g, 256>>>(xin, norm_w + i * CH, norm_b + i * CH, xnh, xnl);
        }
        {   // in_proj: (25088,256)x(1024,256)^T -> f32 xz
            dim3 g(1024 / 128, MTOT / 128, 1);
            gemm_cp<4,0><<<g, 256, SMEM_NI4>>>(xnh, xnl,
                wh + wb + W_IN_OFF, wl + wb + W_IN_OFF, xz, MTOT, 2 * DI, CH);
        }
        // conv + silu -> split planes
        conv_silu_kernel<<<(MTOT * DI / 4) / 256, 256>>>(conv_w + i * DI * DCONV,
                                                         conv_b + i * DI);
        {   // x_proj: split-K=4 -> 4 partial (25088,48) buffers
            dim3 g(1, MTOT / 128, 4);
            gemm_cp<2,0><<<g, 256, SMEM_NI2>>>(xch, xcl,
                wh + wb + W_XP_OFF, wl + wb + W_XP_OFF, xdp, MTOT, 48, DI);
        }
        {   // selective scan (fused dt_proj, sums partials) -> split y planes
            dim3 g(B_SZ, DI / 64);
            scan_kernel<<<g, 128>>>(A_log + i * DI * DS, Dp + i * DI,
                                    dtp_w + (size_t)i * DI * DTR, dtp_b + i * DI);
        }
        {   // out_proj: (25088,512)x(256,512)^T -> (B,256,L)
            dim3 g(256 / 128, MTOT / 128, 1);
            gemm_cp<4,1><<<g, 256, SMEM_NI4>>>(yh, yl,
                wh + wb + W_OUT_OFF, wl + wb + W_OUT_OFF, xout, MTOT, CH, DI);
        }
    }
}

// round 7
// speedup vs baseline: 2.3020x; 2.2229x over previous
#include <cuda_runtime.h>
#include <cuda_bf16.h>
#include <math.h>
#include <stdint.h>

#define B_SZ   32
#define CH     256
#define L_SEQ  784
#define DI     512
#define DS     16
#define DCONV  4
#define DTR    16
#define MTOT   (B_SZ * L_SEQ)   // 25088
#define NCH    16
#define CL     49               // 16 * 49 = 784

// ---------------- scratch (static __device__, no allocation) ----------------
__device__ float g_xn  [(size_t)MTOT * CH];
__device__ float g_xz  [(size_t)MTOT * 2 * DI];
__device__ float g_xc  [(size_t)MTOT * DI];
__device__ float g_xdbl[(size_t)MTOT * 48];
__device__ float g_y   [(size_t)MTOT * DI];
__device__ float g_xbuf[(size_t)B_SZ * CH * L_SEQ];
__device__ float g_dtv [(size_t)MTOT * DI];
__device__ float g_hloc[(size_t)B_SZ * NCH * DS * DI];
__device__ float g_hc0 [(size_t)B_SZ * NCH * DS * DI];
__device__ float g_sdt [(size_t)B_SZ * NCH * DI];

// ============================================================================
// bf16 split helpers (GEMM converts f32 -> hi/lo bf16 in-kernel; 3-term mma)
// ============================================================================
__device__ __forceinline__ void bf16_split_pack(float x0, float x1,
                                                uint32_t& hi, uint32_t& lo) {
    __nv_bfloat16 h0 = __float2bfloat16(x0);
    __nv_bfloat16 h1 = __float2bfloat16(x1);
    float r0 = x0 - __bfloat162float(h0);
    float r1 = x1 - __bfloat162float(h1);
    __nv_bfloat16 l0 = __float2bfloat16(r0);
    __nv_bfloat16 l1 = __float2bfloat16(r1);
    hi = ((uint32_t)__bfloat16_as_ushort(h1) << 16) | __bfloat16_as_ushort(h0);
    lo = ((uint32_t)__bfloat16_as_ushort(l1) << 16) | __bfloat16_as_ushort(l0);
}
__device__ __forceinline__ void ldsm4(uint32_t q[4], uint32_t addr) {
    asm volatile("ldmatrix.sync.aligned.m8n8.x4.shared.b16 {%0,%1,%2,%3}, [%4];"
                 : "=r"(q[0]), "=r"(q[1]), "=r"(q[2]), "=r"(q[3]) : "r"(addr));
}
__device__ __forceinline__ void mma_bf16(float* c, const uint32_t a[4],
                                         uint32_t b0, uint32_t b1) {
    asm volatile("mma.sync.aligned.m16n8k16.row.col.f32.bf16.bf16.f32 "
                 "{%0,%1,%2,%3},{%4,%5,%6,%7},{%8,%9},{%0,%1,%2,%3};"
                 : "+f"(c[0]), "+f"(c[1]), "+f"(c[2]), "+f"(c[3])
                 : "r"(a[0]), "r"(a[1]), "r"(a[2]), "r"(a[3]), "r"(b0), "r"(b1));
}

// ============================================================================
// R4 GEMM (best measured): C[M,N] = A[M,K]*B[N,K]^T, fp32 via 3-term bf16.
// BM=128, BN=NI*32, BK=16, 256 thr, warps 2(m) x 4(n). Double buffered.
// ============================================================================
template<int NI, int TRANS>
__global__ void __launch_bounds__(256)
gemm_bf(const float* __restrict__ A, const float* __restrict__ Bw,
        float* __restrict__ C, int M, int N, int K) {
    constexpr int RS     = 12;
    constexpr int A_U32  = 128 * RS;
    constexpr int BROWS  = NI * 32;
    constexpr int B_U32  = BROWS * RS;
    constexpr int STAGE  = 2 * A_U32 + 2 * B_U32;
    constexpr int NBF    = (NI == 4) ? 8 : 4;

    extern __shared__ uint32_t smu[];
    const uint32_t sb0 = (uint32_t)__cvta_generic_to_shared(smu);

    const int tid  = threadIdx.x;
    const int bm   = blockIdx.y * 128;
    const int bn   = blockIdx.x * BROWS;
    const int warp = tid >> 5, lane = tid & 31;
    const int wm   = warp & 1, wn = warp >> 1;
    const int lm   = lane >> 3, lr = lane & 7;
    const int r    = lane >> 2, cc = lane & 3;

    const int pr = tid >> 1, ph = tid & 1;
    const int br2 = tid >> 2, bq2 = tid & 3;

    float acc[4][NI][4];
    #pragma unroll
    for (int i = 0; i < 4; i++)
        #pragma unroll
        for (int j = 0; j < NI; j++)
            #pragma unroll
            for (int v = 0; v < 4; v++) acc[i][j][v] = 0.0f;

    const int KT = K >> 4;
    float pA[8], pB[NBF];

    {
        const float* pa = A + (size_t)(bm + pr) * K + ph * 8;
        float4 f0 = *reinterpret_cast<const float4*>(pa);
        float4 f1 = *reinterpret_cast<const float4*>(pa + 4);
        pA[0]=f0.x; pA[1]=f0.y; pA[2]=f0.z; pA[3]=f0.w;
        pA[4]=f1.x; pA[5]=f1.y; pA[6]=f1.z; pA[7]=f1.w;
        if (NI == 4) {
            int nb = min(bn + pr, N - 1);
            const float* pb = Bw + (size_t)nb * K + ph * 8;
            float4 g0 = *reinterpret_cast<const float4*>(pb);
            float4 g1 = *reinterpret_cast<const float4*>(pb + 4);
            pB[0]=g0.x; pB[1]=g0.y; pB[2]=g0.z; pB[3]=g0.w;
            pB[4]=g1.x; pB[5]=g1.y; pB[6]=g1.z; pB[7]=g1.w;
        } else {
            int nb = min(bn + br2, N - 1);
            float4 g0 = *reinterpret_cast<const float4*>(Bw + (size_t)nb * K + bq2 * 4);
            pB[0]=g0.x; pB[1]=g0.y; pB[2]=g0.z; pB[3]=g0.w;
        }
    }

    for (int kt = 0; kt < KT; kt++) {
        const int s = kt & 1;
        uint32_t* stg = smu + s * STAGE;

        {
            uint32_t h[4], l[4];
            bf16_split_pack(pA[0], pA[1], h[0], l[0]);
            bf16_split_pack(pA[2], pA[3], h[1], l[1]);
            bf16_split_pack(pA[4], pA[5], h[2], l[2]);
            bf16_split_pack(pA[6], pA[7], h[3], l[3]);
            *reinterpret_cast<uint4*>(stg + pr * RS + ph * 4) =
                make_uint4(h[0], h[1], h[2], h[3]);
            *reinterpret_cast<uint4*>(stg + A_U32 + pr * RS + ph * 4) =
                make_uint4(l[0], l[1], l[2], l[3]);
            if (NI == 4) {
                bf16_split_pack(pB[0], pB[1], h[0], l[0]);
                bf16_split_pack(pB[2], pB[3], h[1], l[1]);
                bf16_split_pack(pB[4], pB[5], h[2], l[2]);
                bf16_split_pack(pB[6], pB[7], h[3], l[3]);
                *reinterpret_cast<uint4*>(stg + 2 * A_U32 + pr * RS + ph * 4) =
                    make_uint4(h[0], h[1], h[2], h[3]);
                *reinterpret_cast<uint4*>(stg + 2 * A_U32 + B_U32 + pr * RS + ph * 4) =
                    make_uint4(l[0], l[1], l[2], l[3]);
            } else {
                bf16_split_pack(pB[0], pB[1], h[0], l[0]);
                bf16_split_pack(pB[2], pB[3], h[1], l[1]);
                *reinterpret_cast<uint2*>(stg + 2 * A_U32 + br2 * RS + bq2 * 2) =
                    make_uint2(h[0], h[1]);
                *reinterpret_cast<uint2*>(stg + 2 * A_U32 + B_U32 + br2 * RS + bq2 * 2) =
                    make_uint2(l[0], l[1]);
            }
        }

        if (kt + 1 < KT) {
            int k0 = (kt + 1) << 4;
            const float* pa = A + (size_t)(bm + pr) * K + k0 + ph * 8;
            float4 f0 = *reinterpret_cast<const float4*>(pa);
            float4 f1 = *reinterpret_cast<const float4*>(pa + 4);
            pA[0]=f0.x; pA[1]=f0.y; pA[2]=f0.z; pA[3]=f0.w;
            pA[4]=f1.x; pA[5]=f1.y; pA[6]=f1.z; pA[7]=f1.w;
            if (NI == 4) {
                int nb = min(bn + pr, N - 1);
                const float* pb = Bw + (size_t)nb * K + k0 + ph * 8;
                float4 g0 = *reinterpret_cast<const float4*>(pb);
                float4 g1 = *reinterpret_cast<const float4*>(pb + 4);
                pB[0]=g0.x; pB[1]=g0.y; pB[2]=g0.z; pB[3]=g0.w;
                pB[4]=g1.x; pB[5]=g1.y; pB[6]=g1.z; pB[7]=g1.w;
            } else {
                int nb = min(bn + br2, N - 1);
                float4 g0 = *reinterpret_cast<const float4*>(Bw + (size_t)nb * K + k0 + bq2 * 4);
                pB[0]=g0.x; pB[1]=g0.y; pB[2]=g0.z; pB[3]=g0.w;
            }
        }

        __syncthreads();

        {
            const uint32_t stb = sb0 + (uint32_t)(s * STAGE) * 4;
            uint32_t BH[NI][2], BL[NI][2];
            #pragma unroll
            for (int tt = 0; tt < NI / 2; tt++) {
                uint32_t rowb = wn * (NI * 8) + tt * 16 + (lm & 1) * 8 + lr;
                uint32_t ad = stb + (2 * A_U32) * 4 + rowb * 48 + (lm >> 1) * 16;
                uint32_t q[4];
                ldsm4(q, ad);
                BH[2*tt][0] = q[0]; BH[2*tt+1][0] = q[1];
                BH[2*tt][1] = q[2]; BH[2*tt+1][1] = q[3];
                ldsm4(q, ad + B_U32 * 4);
                BL[2*tt][0] = q[0]; BL[2*tt+1][0] = q[1];
                BL[2*tt][1] = q[2]; BL[2*tt+1][1] = q[3];
            }
            #pragma unroll
            for (int mi = 0; mi < 4; mi++) {
                uint32_t rowa = wm * 64 + mi * 16 + (lm & 1) * 8 + lr;
                uint32_t ad = stb + rowa * 48 + (lm >> 1) * 16;
                uint32_t AH[4], AL[4];
                ldsm4(AH, ad);
                ldsm4(AL, ad + A_U32 * 4);
                #pragma unroll
                for (int ni = 0; ni < NI; ni++) {
                    mma_bf16(acc[mi][ni], AH, BH[ni][0], BH[ni][1]);
                    mma_bf16(acc[mi][ni], AL, BH[ni][0], BH[ni][1]);
                    mma_bf16(acc[mi][ni], AH, BL[ni][0], BL[ni][1]);
                }
            }
        }
    }

    if (!TRANS) {
        #pragma unroll
        for (int mi = 0; mi < 4; mi++) {
            int row0 = bm + wm * 64 + mi * 16 + r;
            #pragma unroll
            for (int ni = 0; ni < NI; ni++) {
                int col = bn + wn * (NI * 8) + ni * 8 + 2 * cc;
                if (col < N) {
                    *reinterpret_cast<float2*>(C + (size_t)row0 * N + col) =
                        make_float2(acc[mi][ni][0], acc[mi][ni][1]);
                    *reinterpret_cast<float2*>(C + (size_t)(row0 + 8) * N + col) =
                        make_float2(acc[mi][ni][2], acc[mi][ni][3]);
                }
            }
        }
    } else {
        float* ct = reinterpret_cast<float*>(smu);
        __syncthreads();
        #pragma unroll
        for (int half = 0; half < 2; half++) {
            if ((wn >> 1) == half) {
                #pragma unroll
                for (int mi = 0; mi < 4; mi++) {
                    int m0 = wm * 64 + mi * 16 + r;
                    #pragma unroll
                    for (int ni = 0; ni < NI; ni++) {
                        int n0 = (wn - half * 2) * (NI * 8) + ni * 8 + 2 * cc;
                        ct[(n0    ) * 132 + m0    ] = acc[mi][ni][0];
                        ct[(n0 + 1) * 132 + m0    ] = acc[mi][ni][1];
                        ct[(n0    ) * 132 + m0 + 8] = acc[mi][ni][2];
                        ct[(n0 + 1) * 132 + m0 + 8] = acc[mi][ni][3];
                    }
                }
            }
            __syncthreads();
            for (int i = tid; i < 64 * 128; i += 256) {
                int n = i >> 7, m = i & 127;
                int row = bm + m;
                int b = row / L_SEQ;
                int l = row - b * L_SEQ;
                C[((size_t)b * N + bn + half * 64 + n) * L_SEQ + l] = ct[n * 132 + m];
            }
            __syncthreads();
        }
    }
}

// ---------------- LayerNorm, coalesced, (B,C,L) -> (B*L, C) ------------------
__global__ void ln_kernel(const float* __restrict__ x,
                          const float* __restrict__ w,
                          const float* __restrict__ bb,
                          float* __restrict__ out) {
    __shared__ float s[256][17];
    int l0 = blockIdx.x * 16;
    int b  = blockIdx.y;
    int tid = threadIdx.x;

    for (int i = tid; i < 256 * 16; i += 256) {
        int c = i >> 4, l = i & 15;
        s[c][l] = x[((size_t)b * CH + c) * L_SEQ + l0 + l];
    }
    __syncthreads();

    int l = tid >> 4, part = tid & 15;
    float a = 0.f, q = 0.f;
    #pragma unroll
    for (int j = 0; j < 16; j++) {
        float v = s[part + 16 * j][l];
        a += v;
        q = fmaf(v, v, q);
    }
    #pragma unroll
    for (int o = 1; o < 16; o <<= 1) {
        a += __shfl_xor_sync(0xffffffffu, a, o);
        q += __shfl_xor_sync(0xffffffffu, q, o);
    }
    float mu  = a * (1.0f / CH);
    float var = q * (1.0f / CH) - mu * mu;
    float inv = rsqrtf(var + 1e-5f);

    size_t base = (size_t)(b * L_SEQ + l0 + l) * CH;
    #pragma unroll
    for (int j = 0; j < 16; j++) {
        int c = part + 16 * j;
        out[base + c] = (s[c][l] - mu) * inv * w[c] + bb[c];
    }
}

// ---------------- causal conv (k=4) + SiLU, 4 l's x 4 d's per thread ----------
__global__ void conv_silu_kernel(const float* __restrict__ cw,
                                 const float* __restrict__ cb) {
    int idx = blockIdx.x * 256 + threadIdx.x;    // (MTOT/4)*(DI/4)
    int dq  = idx & 127;
    int d   = dq << 2;
    int blq = idx >> 7;
    int b   = blq / 196, lt = blq % 196;
    int l0  = lt * 4;
    size_t row0 = (size_t)b * L_SEQ + l0;

    float4 w0 = *reinterpret_cast<const float4*>(cw + (d + 0) * 4);
    float4 w1 = *reinterpret_cast<const float4*>(cw + (d + 1) * 4);
    float4 w2 = *reinterpret_cast<const float4*>(cw + (d + 2) * 4);
    float4 w3 = *reinterpret_cast<const float4*>(cw + (d + 3) * 4);
    const float wk[4][4] = {{w0.x, w1.x, w2.x, w3.x}, {w0.y, w1.y, w2.y, w3.y},
                            {w0.z, w1.z, w2.z, w3.z}, {w0.w, w1.w, w2.w, w3.w}};
    float4 bias4 = *reinterpret_cast<const float4*>(cb + d);

    float4 xx[7];
    #pragma unroll
    for (int k = 0; k < 7; k++) {
        int l = l0 - 3 + k;
        xx[k] = (l >= 0)
            ? *reinterpret_cast<const float4*>(g_xz + (row0 - 3 + k) * (2 * DI) + d)
            : make_float4(0.f, 0.f, 0.f, 0.f);
    }

    #pragma unroll
    for (int j = 0; j < 4; j++) {
        float4 acc = bias4;
        #pragma unroll
        for (int k = 0; k < 4; k++) {
            float4 v = xx[j + k];
            acc.x = fmaf(v.x, wk[k][0], acc.x);
            acc.y = fmaf(v.y, wk[k][1], acc.y);
            acc.z = fmaf(v.z, wk[k][2], acc.z);
            acc.w = fmaf(v.w, wk[k][3], acc.w);
        }
        acc.x = acc.x / (1.0f + __expf(-acc.x));
        acc.y = acc.y / (1.0f + __expf(-acc.y));
        acc.z = acc.z / (1.0f + __expf(-acc.z));
        acc.w = acc.w / (1.0f + __expf(-acc.w));
        *reinterpret_cast<float4*>(g_xc + (row0 + j) * DI + d) = acc;
    }
}

// ============================================================================
// Chunked selective scan: pass1 (local scans) / pass2 (carry) / pass3 (emit y)
// ============================================================================
__device__ __forceinline__ void dA_build(float dtv, int half, bool powok,
                                         const float* a, float dA[8]) {
    if (powok) {
        float r1 = __expf(-dtv);
        float r2 = r1 * r1, r3 = r2 * r1, r4 = r2 * r2;
        dA[0] = r1; dA[1] = r2; dA[2] = r3; dA[3] = r4;
        dA[4] = r4 * r1; dA[5] = r4 * r2; dA[6] = r4 * r3; dA[7] = r4 * r4;
        if (half) {
            float r8 = r4 * r4;
            #pragma unroll
            for (int s = 0; s < 8; s++) dA[s] *= r8;
        }
    } else {
        #pragma unroll
        for (int s = 0; s < 8; s++) dA[s] = __expf(dtv * a[s]);
    }
}

__global__ void __launch_bounds__(128)
scan_p1(const float* __restrict__ A_log,
        const float* __restrict__ dtw, const float* __restrict__ dtb) {
    int b  = blockIdx.x, gy = blockIdx.y, ch = blockIdx.z;
    int tid = threadIdx.x;
    int dl = tid >> 1, half = tid & 1;
    int d  = gy * 64 + dl, d0 = gy * 64;

    __shared__ float sR[CL][32];   // dt_r | B
    __shared__ float sX[CL][64];

    size_t rbase = (size_t)b * L_SEQ + ch * CL;
    for (int i = tid; i < CL * 32; i += 128) {
        int st = i >> 5, j = i & 31;
        sR[st][j] = g_xdbl[(rbase + st) * 48 + j];
    }
    for (int i = tid; i < CL * 64; i += 128) {
        int st = i >> 6, j = i & 63;
        sX[st][j] = g_xc[(rbase + st) * DI + d0 + j];
    }
    __syncthreads();

    float w[DTR];
    #pragma unroll
    for (int i = 0; i < DTR; i++) w[i] = dtw[d * DTR + i];
    float bias = dtb[d];

    float a[8];
    bool powok = true;
    #pragma unroll
    for (int s = 0; s < 8; s++) {
        a[s] = -__expf(A_log[d * DS + half * 8 + s]);
        float kf = (float)(half * 8 + s + 1);
        powok = powok && (fabsf(-a[s] - kf) < 1e-3f * kf);
    }

    float h[8];
    #pragma unroll
    for (int s = 0; s < 8; s++) h[s] = 0.0f;
    float sumdt = 0.0f;

    for (int st = 0; st < CL; st++) {
        float s0 = 0.f, s1 = 0.f, s2 = 0.f, s3 = 0.f;
        #pragma unroll
        for (int i = 0; i < 4; i++) {
            s0 = fmaf(w[i],      sR[st][i],      s0);
            s1 = fmaf(w[4 + i],  sR[st][4 + i],  s1);
            s2 = fmaf(w[8 + i],  sR[st][8 + i],  s2);
            s3 = fmaf(w[12 + i], sR[st][12 + i], s3);
        }
        float dtl = bias + ((s0 + s1) + (s2 + s3));
        float dtv = (dtl > 20.0f) ? dtl : log1pf(__expf(dtl));
        if (half == 0) g_dtv[(rbase + st) * DI + d] = dtv;
        sumdt += dtv;

        float dtx = dtv * sX[st][dl];
        float dA[8];
        dA_build(dtv, half, powok, a, dA);
        #pragma unroll
        for (int s = 0; s < 8; s++)
            h[s] = fmaf(h[s], dA[s], dtx * sR[st][16 + half * 8 + s]);
    }

    size_t hb = (((size_t)b * NCH + ch) * DS + half * 8) * DI + d;
    #pragma unroll
    for (int s = 0; s < 8; s++) g_hloc[hb + (size_t)s * DI] = h[s];
    if (half == 0) g_sdt[((size_t)b * NCH + ch) * DI + d] = sumdt;
}

__global__ void __launch_bounds__(128)
scan_p2(const float* __restrict__ A_log) {
    int idx = blockIdx.x * 128 + threadIdx.x;   // b*DI + d, 16384 total
    int b = idx >> 9, d = idx & (DI - 1);

    float a[16];
    bool powok = true;
    #pragma unroll
    for (int s = 0; s < 16; s++) {
        a[s] = -__expf(A_log[d * DS + s]);
        float kf = (float)(s + 1);
        powok = powok && (fabsf(-a[s] - kf) < 1e-3f * kf);
    }

    float H[16];
    #pragma unroll
    for (int s = 0; s < 16; s++) H[s] = 0.0f;

    for (int c = 0; c < NCH; c++) {
        size_t hb = (((size_t)b * NCH + c) * DS) * DI + d;
        #pragma unroll
        for (int s = 0; s < 16; s++) g_hc0[hb + (size_t)s * DI] = H[s];
        float sdt = g_sdt[((size_t)b * NCH + c) * DI + d];
        float q[16];
        if (powok) {
            float r1 = __expf(-sdt);
            float r2 = r1 * r1, r3 = r2 * r1, r4 = r2 * r2;
            q[0]=r1; q[1]=r2; q[2]=r3; q[3]=r4;
            q[4]=r4*r1; q[5]=r4*r2; q[6]=r4*r3; q[7]=r4*r4;
            float r8 = r4 * r4;
            #pragma unroll
            for (int s = 0; s < 8; s++) q[8 + s] = q[s] * r8;
        } else {
            #pragma unroll
            for (int s = 0; s < 16; s++) q[s] = __expf(sdt * a[s]);
        }
        #pragma unroll
        for (int s = 0; s < 16; s++)
            H[s] = fmaf(H[s], q[s], g_hloc[hb + (size_t)s * DI]);
    }
}

__global__ void __launch_bounds__(128)
scan_p3(const float* __restrict__ A_log, const float* __restrict__ Dp) {
    int b  = blockIdx.x, gy = blockIdx.y, ch = blockIdx.z;
    int tid = threadIdx.x;
    int dl = tid >> 1, half = tid & 1;
    int d  = gy * 64 + dl, d0 = gy * 64;

    __shared__ float sBC[CL][32];   // B | C
    __shared__ float sX[CL][64];
    __shared__ float sDT[CL][64];
    __shared__ float sZ[CL][64];

    size_t rbase = (size_t)b * L_SEQ + ch * CL;
    for (int i = tid; i < CL * 32; i += 128) {
        int st = i >> 5, j = i & 31;
        sBC[st][j] = g_xdbl[(rbase + st) * 48 + 16 + j];
    }
    for (int i = tid; i < CL * 64; i += 128) {
        int st = i >> 6, j = i & 63;
        sX [st][j] = g_xc [(rbase + st) * DI + d0 + j];
        sDT[st][j] = g_dtv[(rbase + st) * DI + d0 + j];
        sZ [st][j] = g_xz [(rbase + st) * (2 * DI) + DI + d0 + j];
    }
    __syncthreads();

    float a[8];
    bool powok = true;
    #pragma unroll
    for (int s = 0; s < 8; s++) {
        a[s] = -__expf(A_log[d * DS + half * 8 + s]);
        float kf = (float)(half * 8 + s + 1);
        powok = powok && (fabsf(-a[s] - kf) < 1e-3f * kf);
    }
    float Dd = Dp[d];

    float h[8];
    size_t hb = (((size_t)b * NCH + ch) * DS + half * 8) * DI + d;
    #pragma unroll
    for (int s = 0; s < 8; s++) h[s] = g_hc0[hb + (size_t)s * DI];

    for (int st = 0; st < CL; st++) {
        float dtv = sDT[st][dl];
        float xv  = sX[st][dl];
        float dtx = dtv * xv;
        float dA[8];
        dA_build(dtv, half, powok, a, dA);
        float y0 = 0.f, y1 = 0.f;
        #pragma unroll
        for (int s = 0; s < 4; s++) {
            h[s] = fmaf(h[s], dA[s], dtx * sBC[st][half * 8 + s]);
            y0   = fmaf(h[s], sBC[st][16 + half * 8 + s], y0);
        }
        #pragma unroll
        for (int s = 4; s < 8; s++) {
            h[s] = fmaf(h[s], dA[s], dtx * sBC[st][half * 8 + s]);
            y1   = fmaf(h[s], sBC[st][16 + half * 8 + s], y1);
        }
        float yacc = y0 + y1;
        yacc += __shfl_xor_sync(0xffffffffu, yacc, 1);
        if (half == 0) {
            float zv = sZ[st][dl];
            g_y[(rbase + st) * DI + d] =
                fmaf(xv, Dd, yacc) * (zv / (1.0f + __expf(-zv)));
        }
    }
}

// ------------------------------- launcher -------------------------------------
extern "C" void kernel_launch(void* const* d_in, const int* in_sizes, int n_in,
                              void* d_out, int out_size) {
    const float* bbox   = (const float*)d_in[0];
    const float* norm_w = (const float*)d_in[1];
    const float* norm_b = (const float*)d_in[2];
    const float* in_w   = (const float*)d_in[3];
    const float* conv_w = (const float*)d_in[4];
    const float* conv_b = (const float*)d_in[5];
    const float* xp_w   = (const float*)d_in[6];
    const float* dtp_w  = (const float*)d_in[7];
    const float* dtp_b  = (const float*)d_in[8];
    const float* A_log  = (const float*)d_in[9];
    const float* Dp     = (const float*)d_in[10];
    const float* out_w  = (const float*)d_in[11];
    float* out = (float*)d_out;

    cudaFuncSetAttribute(gemm_bf<4,0>, cudaFuncAttributeMaxDynamicSharedMemorySize, 49152);
    cudaFuncSetAttribute(gemm_bf<4,1>, cudaFuncAttributeMaxDynamicSharedMemorySize, 49152);
    cudaFuncSetAttribute(gemm_bf<2,0>, cudaFuncAttributeMaxDynamicSharedMemorySize, 36864);

    float *xn, *xz, *xc, *xdbl, *yy, *xbuf;
    cudaGetSymbolAddress((void**)&xn,   g_xn);
    cudaGetSymbolAddress((void**)&xz,   g_xz);
    cudaGetSymbolAddress((void**)&xc,   g_xc);
    cudaGetSymbolAddress((void**)&xdbl, g_xdbl);
    cudaGetSymbolAddress((void**)&yy,   g_y);
    cudaGetSymbolAddress((void**)&xbuf, g_xbuf);

    for (int i = 0; i < 2; i++) {
        const float* xin = (i == 0) ? bbox : xbuf;
        float* xout      = (i == 0) ? xbuf : out;

        {   // layernorm
            dim3 g(49, 32);
            ln_kernel<<<g, 256>>>(xin, norm_w + i * CH, norm_b + i * CH, xn);
        }
        {   // in_proj
            dim3 g(1024 / 128, MTOT / 128);
            gemm_bf<4,0><<<g, 256, 49152>>>(xn, in_w + (size_t)i * 2 * DI * CH, xz,
                                            MTOT, 2 * DI, CH);
        }
        // conv + silu (4-l tiled)
        conv_silu_kernel<<<(MTOT / 4) * (DI / 4) / 256, 256>>>(conv_w + i * DI * DCONV,
                                                               conv_b + i * DI);
        {   // x_proj
            dim3 g(1, MTOT / 128);
            gemm_bf<2,0><<<g, 256, 36864>>>(xc, xp_w + (size_t)i * 48 * DI, xdbl,
                                            MTOT, 48, DI);
        }
        {   // chunked scan
            dim3 g1(B_SZ, DI / 64, NCH);
            scan_p1<<<g1, 128>>>(A_log + i * DI * DS,
                                 dtp_w + (size_t)i * DI * DTR, dtp_b + i * DI);
            scan_p2<<<(B_SZ * DI) / 128, 128>>>(A_log + i * DI * DS);
            scan_p3<<<g1, 128>>>(A_log + i * DI * DS, Dp + i * DI);
        }
        {   // out_proj -> (B,256,L)
            dim3 g(256 / 128, MTOT / 128);
            gemm_bf<4,1><<<g, 256, 49152>>>(yy, out_w + (size_t)i * CH * DI, xout,
                                            MTOT, CH, DI);
        }
    }
}

// round 9
// speedup vs baseline: 2.5455x; 1.1058x over previous
#include <cuda_runtime.h>
#include <cuda_fp16.h>
#include <math.h>
#include <stdint.h>

#define B_SZ   32
#define CH     256
#define L_SEQ  784
#define DI     512
#define DS     16
#define DCONV  4
#define DTR    16
#define MTOT   (B_SZ * L_SEQ)   // 25088
#define NCH    16
#define CL     49               // 16 * 49 = 784

// ---------------- scratch (static __device__, no allocation) ----------------
__device__ float g_xn  [(size_t)MTOT * CH];
__device__ float g_xz  [(size_t)MTOT * 2 * DI];
__device__ float g_xc  [(size_t)MTOT * DI];
__device__ float g_xdp [4][(size_t)MTOT * 48];
__device__ float g_y   [(size_t)MTOT * DI];
__device__ float g_xbuf[(size_t)B_SZ * CH * L_SEQ];
__device__ float g_dtv [(size_t)MTOT * DI];
__device__ float g_hloc[(size_t)B_SZ * NCH * DS * DI];
__device__ float g_hc0 [(size_t)B_SZ * NCH * DS * DI];
__device__ float g_sdt [(size_t)B_SZ * NCH * DI];

// ============================================================================
// fp16 split helpers: A -> hi/lo fp16 planes, B -> single fp16 plane.
// 2-term mma: a_h*b + a_l*b ; dropped a*b_lo ~ 2^-12 relative.
// ============================================================================
__device__ __forceinline__ void f16_split_pack(float x0, float x1,
                                               uint32_t& hi, uint32_t& lo) {
    __half h0 = __float2half_rn(x0);
    __half h1 = __float2half_rn(x1);
    float r0 = x0 - __half2float(h0);
    float r1 = x1 - __half2float(h1);
    __half l0 = __float2half_rn(r0);
    __half l1 = __float2half_rn(r1);
    hi = ((uint32_t)__half_as_ushort(h1) << 16) | __half_as_ushort(h0);
    lo = ((uint32_t)__half_as_ushort(l1) << 16) | __half_as_ushort(l0);
}
__device__ __forceinline__ uint32_t f16_pack(float x0, float x1) {
    __half2 h = __floats2half2_rn(x0, x1);
    return *reinterpret_cast<uint32_t*>(&h);
}
__device__ __forceinline__ void ldsm4(uint32_t q[4], uint32_t addr) {
    asm volatile("ldmatrix.sync.aligned.m8n8.x4.shared.b16 {%0,%1,%2,%3}, [%4];"
                 : "=r"(q[0]), "=r"(q[1]), "=r"(q[2]), "=r"(q[3]) : "r"(addr));
}
__device__ __forceinline__ void mma_f16(float* c, const uint32_t a[4],
                                        uint32_t b0, uint32_t b1) {
    asm volatile("mma.sync.aligned.m16n8k16.row.col.f32.f16.f16.f32 "
                 "{%0,%1,%2,%3},{%4,%5,%6,%7},{%8,%9},{%0,%1,%2,%3};"
                 : "+f"(c[0]), "+f"(c[1]), "+f"(c[2]), "+f"(c[3])
                 : "r"(a[0]), "r"(a[1]), "r"(a[2]), "r"(a[3]), "r"(b0), "r"(b1));
}

// ============================================================================
// GEMM C[M,N] = A[M,K]*B[N,K]^T, fp32 via fp16 2-term split.
// BM=128, BN=NI*32, BK=16, 256 thr, warps 2(m) x 4(n). Double buffered,
// 1 sync/k-tile. gridDim.z = split-K factor (z writes C + z*M*N).
// ============================================================================
template<int NI, int TRANS>
__global__ void __launch_bounds__(256)
gemm_hf(const float* __restrict__ A, const float* __restrict__ Bw,
        float* __restrict__ C, int M, int N, int K) {
    constexpr int RS     = 12;              // u32 per smem row (16 f16 + pad)
    constexpr int A_U32  = 128 * RS;
    constexpr int BROWS  = NI * 32;
    constexpr int B_U32  = BROWS * RS;
    constexpr int STAGE  = 2 * A_U32 + B_U32;
    constexpr int NBF    = (NI == 4) ? 8 : 4;

    extern __shared__ uint32_t smu[];
    const uint32_t sb0 = (uint32_t)__cvta_generic_to_shared(smu);

    const int tid  = threadIdx.x;
    const int bm   = blockIdx.y * 128;
    const int bn   = blockIdx.x * BROWS;
    const int Kloc = K / gridDim.z;
    const int koff = blockIdx.z * Kloc;
    C += (size_t)blockIdx.z * M * N;

    const int warp = tid >> 5, lane = tid & 31;
    const int wm   = warp & 1, wn = warp >> 1;
    const int lm   = lane >> 3, lr = lane & 7;
    const int r    = lane >> 2, cc = lane & 3;

    const int pr = tid >> 1, ph = tid & 1;
    const int br2 = tid >> 2, bq2 = tid & 3;

    float acc[4][NI][4];
    #pragma unroll
    for (int i = 0; i < 4; i++)
        #pragma unroll
        for (int j = 0; j < NI; j++)
            #pragma unroll
            for (int v = 0; v < 4; v++) acc[i][j][v] = 0.0f;

    const int KT = Kloc >> 4;
    float pA[8], pB[NBF];

    {
        const float* pa = A + (size_t)(bm + pr) * K + koff + ph * 8;
        float4 f0 = *reinterpret_cast<const float4*>(pa);
        float4 f1 = *reinterpret_cast<const float4*>(pa + 4);
        pA[0]=f0.x; pA[1]=f0.y; pA[2]=f0.z; pA[3]=f0.w;
        pA[4]=f1.x; pA[5]=f1.y; pA[6]=f1.z; pA[7]=f1.w;
        if (NI == 4) {
            int nb = min(bn + pr, N - 1);
            const float* pb = Bw + (size_t)nb * K + koff + ph * 8;
            float4 g0 = *reinterpret_cast<const float4*>(pb);
            float4 g1 = *reinterpret_cast<const float4*>(pb + 4);
            pB[0]=g0.x; pB[1]=g0.y; pB[2]=g0.z; pB[3]=g0.w;
            pB[4]=g1.x; pB[5]=g1.y; pB[6]=g1.z; pB[7]=g1.w;
        } else {
            int nb = min(bn + br2, N - 1);
            float4 g0 = *reinterpret_cast<const float4*>(Bw + (size_t)nb * K + koff + bq2 * 4);
            pB[0]=g0.x; pB[1]=g0.y; pB[2]=g0.z; pB[3]=g0.w;
        }
    }

    for (int kt = 0; kt < KT; kt++) {
        const int s = kt & 1;
        uint32_t* stg = smu + s * STAGE;

        // ---- producer: A split (hi/lo), B single-plane fp16 ----
        {
            uint32_t h[4], l[4];
            f16_split_pack(pA[0], pA[1], h[0], l[0]);
            f16_split_pack(pA[2], pA[3], h[1], l[1]);
            f16_split_pack(pA[4], pA[5], h[2], l[2]);
            f16_split_pack(pA[6], pA[7], h[3], l[3]);
            *reinterpret_cast<uint4*>(stg + pr * RS + ph * 4) =
                make_uint4(h[0], h[1], h[2], h[3]);
            *reinterpret_cast<uint4*>(stg + A_U32 + pr * RS + ph * 4) =
                make_uint4(l[0], l[1], l[2], l[3]);
            if (NI == 4) {
                *reinterpret_cast<uint4*>(stg + 2 * A_U32 + pr * RS + ph * 4) =
                    make_uint4(f16_pack(pB[0], pB[1]), f16_pack(pB[2], pB[3]),
                               f16_pack(pB[4], pB[5]), f16_pack(pB[6], pB[7]));
            } else {
                *reinterpret_cast<uint2*>(stg + 2 * A_U32 + br2 * RS + bq2 * 2) =
                    make_uint2(f16_pack(pB[0], pB[1]), f16_pack(pB[2], pB[3]));
            }
        }

        // ---- prefetch next tile ----
        if (kt + 1 < KT) {
            int k0 = koff + ((kt + 1) << 4);
            const float* pa = A + (size_t)(bm + pr) * K + k0 + ph * 8;
            float4 f0 = *reinterpret_cast<const float4*>(pa);
            float4 f1 = *reinterpret_cast<const float4*>(pa + 4);
            pA[0]=f0.x; pA[1]=f0.y; pA[2]=f0.z; pA[3]=f0.w;
            pA[4]=f1.x; pA[5]=f1.y; pA[6]=f1.z; pA[7]=f1.w;
            if (NI == 4) {
                int nb = min(bn + pr, N - 1);
                const float* pb = Bw + (size_t)nb * K + k0 + ph * 8;
                float4 g0 = *reinterpret_cast<const float4*>(pb);
                float4 g1 = *reinterpret_cast<const float4*>(pb + 4);
                pB[0]=g0.x; pB[1]=g0.y; pB[2]=g0.z; pB[3]=g0.w;
                pB[4]=g1.x; pB[5]=g1.y; pB[6]=g1.z; pB[7]=g1.w;
            } else {
                int nb = min(bn + br2, N - 1);
                float4 g0 = *reinterpret_cast<const float4*>(Bw + (size_t)nb * K + k0 + bq2 * 4);
                pB[0]=g0.x; pB[1]=g0.y; pB[2]=g0.z; pB[3]=g0.w;
            }
        }

        __syncthreads();

        // ---- consumer: LDSM + 2-term fp16 mma ----
        {
            const uint32_t stb = sb0 + (uint32_t)(s * STAGE) * 4;
            uint32_t BH[NI][2];
            #pragma unroll
            for (int tt = 0; tt < NI / 2; tt++) {
                uint32_t rowb = wn * (NI * 8) + tt * 16 + (lm & 1) * 8 + lr;
                uint32_t ad = stb + (2 * A_U32) * 4 + rowb * 48 + (lm >> 1) * 16;
                uint32_t q[4];
                ldsm4(q, ad);
                BH[2*tt][0] = q[0]; BH[2*tt+1][0] = q[1];
                BH[2*tt][1] = q[2]; BH[2*tt+1][1] = q[3];
            }
            #pragma unroll
            for (int mi = 0; mi < 4; mi++) {
                uint32_t rowa = wm * 64 + mi * 16 + (lm & 1) * 8 + lr;
                uint32_t ad = stb + rowa * 48 + (lm >> 1) * 16;
                uint32_t AH[4], AL[4];
                ldsm4(AH, ad);
                ldsm4(AL, ad + A_U32 * 4);
                #pragma unroll
                for (int ni = 0; ni < NI; ni++) {
                    mma_f16(acc[mi][ni], AH, BH[ni][0], BH[ni][1]);
                    mma_f16(acc[mi][ni], AL, BH[ni][0], BH[ni][1]);
                }
            }
        }
    }

    if (!TRANS) {
        #pragma unroll
        for (int mi = 0; mi < 4; mi++) {
            int row0 = bm + wm * 64 + mi * 16 + r;
            #pragma unroll
            for (int ni = 0; ni < NI; ni++) {
                int col = bn + wn * (NI * 8) + ni * 8 + 2 * cc;
                if (col < N) {
                    *reinterpret_cast<float2*>(C + (size_t)row0 * N + col) =
                        make_float2(acc[mi][ni][0], acc[mi][ni][1]);
                    *reinterpret_cast<float2*>(C + (size_t)(row0 + 8) * N + col) =
                        make_float2(acc[mi][ni][2], acc[mi][ni][3]);
                }
            }
        }
    } else {
        float* ct = reinterpret_cast<float*>(smu);
        __syncthreads();
        #pragma unroll
        for (int half = 0; half < 2; half++) {
            if ((wn >> 1) == half) {
                #pragma unroll
                for (int mi = 0; mi < 4; mi++) {
                    int m0 = wm * 64 + mi * 16 + r;
                    #pragma unroll
                    for (int ni = 0; ni < NI; ni++) {
                        int n0 = (wn - half * 2) * (NI * 8) + ni * 8 + 2 * cc;
                        ct[(n0    ) * 132 + m0    ] = acc[mi][ni][0];
                        ct[(n0 + 1) * 132 + m0    ] = acc[mi][ni][1];
                        ct[(n0    ) * 132 + m0 + 8] = acc[mi][ni][2];
                        ct[(n0 + 1) * 132 + m0 + 8] = acc[mi][ni][3];
                    }
                }
            }
            __syncthreads();
            for (int i = tid; i < 64 * 128; i += 256) {
                int n = i >> 7, m = i & 127;
                int row = bm + m;
                int b = row / L_SEQ;
                int l = row - b * L_SEQ;
                C[((size_t)b * N + bn + half * 64 + n) * L_SEQ + l] = ct[n * 132 + m];
            }
            __syncthreads();
        }
    }
}

// ---------------- LayerNorm, coalesced, (B,C,L) -> (B*L, C) ------------------
__global__ void ln_kernel(const float* __restrict__ x,
                          const float* __restrict__ w,
                          const float* __restrict__ bb,
                          float* __restrict__ out) {
    __shared__ float s[256][17];
    int l0 = blockIdx.x * 16;
    int b  = blockIdx.y;
    int tid = threadIdx.x;

    for (int i = tid; i < 256 * 16; i += 256) {
        int c = i >> 4, l = i & 15;
        s[c][l] = x[((size_t)b * CH + c) * L_SEQ + l0 + l];
    }
    __syncthreads();

    int l = tid >> 4, part = tid & 15;
    float a = 0.f, q = 0.f;
    #pragma unroll
    for (int j = 0; j < 16; j++) {
        float v = s[part + 16 * j][l];
        a += v;
        q = fmaf(v, v, q);
    }
    #pragma unroll
    for (int o = 1; o < 16; o <<= 1) {
        a += __shfl_xor_sync(0xffffffffu, a, o);
        q += __shfl_xor_sync(0xffffffffu, q, o);
    }
    float mu  = a * (1.0f / CH);
    float var = q * (1.0f / CH) - mu * mu;
    float inv = rsqrtf(var + 1e-5f);

    size_t base = (size_t)(b * L_SEQ + l0 + l) * CH;
    #pragma unroll
    for (int j = 0; j < 16; j++) {
        int c = part + 16 * j;
        out[base + c] = (s[c][l] - mu) * inv * w[c] + bb[c];
    }
}

// ---------------- causal conv (k=4) + SiLU, 4 l's x 4 d's per thread ----------
__global__ void conv_silu_kernel(const float* __restrict__ cw,
                                 const float* __restrict__ cb) {
    int idx = blockIdx.x * 256 + threadIdx.x;
    int dq  = idx & 127;
    int d   = dq << 2;
    int blq = idx >> 7;
    int b   = blq / 196, lt = blq % 196;
    int l0  = lt * 4;
    size_t row0 = (size_t)b * L_SEQ + l0;

    float4 w0 = *reinterpret_cast<const float4*>(cw + (d + 0) * 4);
    float4 w1 = *reinterpret_cast<const float4*>(cw + (d + 1) * 4);
    float4 w2 = *reinterpret_cast<const float4*>(cw + (d + 2) * 4);
    float4 w3 = *reinterpret_cast<const float4*>(cw + (d + 3) * 4);
    const float wk[4][4] = {{w0.x, w1.x, w2.x, w3.x}, {w0.y, w1.y, w2.y, w3.y},
                            {w0.z, w1.z, w2.z, w3.z}, {w0.w, w1.w, w2.w, w3.w}};
    float4 bias4 = *reinterpret_cast<const float4*>(cb + d);

    float4 xx[7];
    #pragma unroll
    for (int k = 0; k < 7; k++) {
        int l = l0 - 3 + k;
        xx[k] = (l >= 0)
            ? *reinterpret_cast<const float4*>(g_xz + (row0 - 3 + k) * (2 * DI) + d)
            : make_float4(0.f, 0.f, 0.f, 0.f);
    }

    #pragma unroll
    for (int j = 0; j < 4; j++) {
        float4 acc = bias4;
        #pragma unroll
        for (int k = 0; k < 4; k++) {
            float4 v = xx[j + k];
            acc.x = fmaf(v.x, wk[k][0], acc.x);
            acc.y = fmaf(v.y, wk[k][1], acc.y);
            acc.z = fmaf(v.z, wk[k][2], acc.z);
            acc.w = fmaf(v.w, wk[k][3], acc.w);
        }
        acc.x = acc.x / (1.0f + __expf(-acc.x));
        acc.y = acc.y / (1.0f + __expf(-acc.y));
        acc.z = acc.z / (1.0f + __expf(-acc.z));
        acc.w = acc.w / (1.0f + __expf(-acc.w));
        *reinterpret_cast<float4*>(g_xc + (row0 + j) * DI + d) = acc;
    }
}

// ============================================================================
// Chunked selective scan (R7, proven) — loaders fuse the split-K=4 reduction.
// ============================================================================
__device__ __forceinline__ void dA_build(float dtv, int half, bool powok,
                                         const float* a, float dA[8]) {
    if (powok) {
        float r1 = __expf(-dtv);
        float r2 = r1 * r1, r3 = r2 * r1, r4 = r2 * r2;
        dA[0] = r1; dA[1] = r2; dA[2] = r3; dA[3] = r4;
        dA[4] = r4 * r1; dA[5] = r4 * r2; dA[6] = r4 * r3; dA[7] = r4 * r4;
        if (half) {
            float r8 = r4 * r4;
            #pragma unroll
            for (int s = 0; s < 8; s++) dA[s] *= r8;
        }
    } else {
        #pragma unroll
        for (int s = 0; s < 8; s++) dA[s] = __expf(dtv * a[s]);
    }
}
__device__ __forceinline__ float xdp_sum(size_t ro) {
    return (g_xdp[0][ro] + g_xdp[1][ro]) + (g_xdp[2][ro] + g_xdp[3][ro]);
}

__global__ void __launch_bounds__(128)
scan_p1(const float* __restrict__ A_log,
        const float* __restrict__ dtw, const float* __restrict__ dtb) {
    int b  = blockIdx.x, gy = blockIdx.y, ch = blockIdx.z;
    int tid = threadIdx.x;
    int dl = tid >> 1, half = tid & 1;
    int d  = gy * 64 + dl, d0 = gy * 64;

    __shared__ float sR[CL][32];   // dt_r | B
    __shared__ float sX[CL][64];

    size_t rbase = (size_t)b * L_SEQ + ch * CL;
    for (int i = tid; i < CL * 32; i += 128) {
        int st = i >> 5, j = i & 31;
        sR[st][j] = xdp_sum((rbase + st) * 48 + j);
    }
    for (int i = tid; i < CL * 64; i += 128) {
        int st = i >> 6, j = i & 63;
        sX[st][j] = g_xc[(rbase + st) * DI + d0 + j];
    }
    __syncthreads();

    float w[DTR];
    #pragma unroll
    for (int i = 0; i < DTR; i++) w[i] = dtw[d * DTR + i];
    float bias = dtb[d];

    float a[8];
    bool powok = true;
    #pragma unroll
    for (int s = 0; s < 8; s++) {
        a[s] = -__expf(A_log[d * DS + half * 8 + s]);
        float kf = (float)(half * 8 + s + 1);
        powok = powok && (fabsf(-a[s] - kf) < 1e-3f * kf);
    }

    float h[8];
    #pragma unroll
    for (int s = 0; s < 8; s++) h[s] = 0.0f;
    float sumdt = 0.0f;

    for (int st = 0; st < CL; st++) {
        float s0 = 0.f, s1 = 0.f, s2 = 0.f, s3 = 0.f;
        #pragma unroll
        for (int i = 0; i < 4; i++) {
            s0 = fmaf(w[i],      sR[st][i],      s0);
            s1 = fmaf(w[4 + i],  sR[st][4 + i],  s1);
            s2 = fmaf(w[8 + i],  sR[st][8 + i],  s2);
            s3 = fmaf(w[12 + i], sR[st][12 + i], s3);
        }
        float dtl = bias + ((s0 + s1) + (s2 + s3));
        float dtv = (dtl > 20.0f) ? dtl : log1pf(__expf(dtl));
        if (half == 0) g_dtv[(rbase + st) * DI + d] = dtv;
        sumdt += dtv;
        float dtx = dtv * sX[st][dl];
        float dA[8];
        dA_build(dtv, half, powok, a, dA);
        #pragma unroll
        for (int s = 0; s < 8; s++)
            h[s] = fmaf(h[s], dA[s], dtx * sR[st][16 + half * 8 + s]);
    }
    size_t hb = (((size_t)b * NCH + ch) * DS + half * 8) * DI + d;
    #pragma unroll
    for (int s = 0; s < 8; s++) g_hloc[hb + (size_t)s * DI] = h[s];
    if (half == 0) g_sdt[((size_t)b * NCH + ch) * DI + d] = sumdt;
}

__global__ void __launch_bounds__(128)
scan_p2(const float* __restrict__ A_log) {
    int idx = blockIdx.x * 128 + threadIdx.x;
    int b = idx >> 9, d = idx & (DI - 1);

    float a[16];
    bool powok = true;
    #pragma unroll
    for (int s = 0; s < 16; s++) {
        a[s] = -__expf(A_log[d * DS + s]);
        float kf = (float)(s + 1);
        powok = powok && (fabsf(-a[s] - kf) < 1e-3f * kf);
    }
    float H[16];
    #pragma unroll
    for (int s = 0; s < 16; s++) H[s] = 0.0f;

    for (int c = 0; c < NCH; c++) {
        size_t hb = (((size_t)b * NCH + c) * DS) * DI + d;
        #pragma unroll
        for (int s = 0; s < 16; s++) g_hc0[hb + (size_t)s * DI] = H[s];
        float sdt = g_sdt[((size_t)b * NCH + c) * DI + d];
        float q[16];
        if (powok) {
            float r1 = __expf(-sdt);
            float r2 = r1 * r1, r3 = r2 * r1, r4 = r2 * r2;
            q[0]=r1; q[1]=r2; q[2]=r3; q[3]=r4;
            q[4]=r4*r1; q[5]=r4*r2; q[6]=r4*r3; q[7]=r4*r4;
            float r8 = r4 * r4;
            #pragma unroll
            for (int s = 0; s < 8; s++) q[8 + s] = q[s] * r8;
        } else {
            #pragma unroll
            for (int s = 0; s < 16; s++) q[s] = __expf(sdt * a[s]);
        }
        #pragma unroll
        for (int s = 0; s < 16; s++)
            H[s] = fmaf(H[s], q[s], g_hloc[hb + (size_t)s * DI]);
    }
}

__global__ void __launch_bounds__(128)
scan_p3(const float* __restrict__ A_log, const float* __restrict__ Dp) {
    int b  = blockIdx.x, gy = blockIdx.y, ch = blockIdx.z;
    int tid = threadIdx.x;
    int dl = tid >> 1, half = tid & 1;
    int d  = gy * 64 + dl, d0 = gy * 64;

    __shared__ float sBC[CL][32];   // B | C
    __shared__ float sX[CL][64];
    __shared__ float sDT[CL][64];
    __shared__ float sZ[CL][64];

    size_t rbase = (size_t)b * L_SEQ + ch * CL;
    for (int i = tid; i < CL * 32; i += 128) {
        int st = i >> 5, j = i & 31;
        sBC[st][j] = xdp_sum((rbase + st) * 48 + 16 + j);
    }
    for (int i = tid; i < CL * 64; i += 128) {
        int st = i >> 6, j = i & 63;
        sX [st][j] = g_xc [(rbase + st) * DI + d0 + j];
        sDT[st][j] = g_dtv[(rbase + st) * DI + d0 + j];
        sZ [st][j] = g_xz [(rbase + st) * (2 * DI) + DI + d0 + j];
    }
    __syncthreads();

    float a[8];
    bool powok = true;
    #pragma unroll
    for (int s = 0; s < 8; s++) {
        a[s] = -__expf(A_log[d * DS + half * 8 + s]);
        float kf = (float)(half * 8 + s + 1);
        powok = powok && (fabsf(-a[s] - kf) < 1e-3f * kf);
    }
    float Dd = Dp[d];

    float h[8];
    size_t hb = (((size_t)b * NCH + ch) * DS + half * 8) * DI + d;
    #pragma unroll
    for (int s = 0; s < 8; s++) h[s] = g_hc0[hb + (size_t)s * DI];

    for (int st = 0; st < CL; st++) {
        float dtv = sDT[st][dl];
        float xv  = sX[st][dl];
        float dtx = dtv * xv;
        float dA[8];
        dA_build(dtv, half, powok, a, dA);
        float y0 = 0.f, y1 = 0.f;
        #pragma unroll
        for (int s = 0; s < 4; s++) {
            h[s] = fmaf(h[s], dA[s], dtx * sBC[st][half * 8 + s]);
            y0   = fmaf(h[s], sBC[st][16 + half * 8 + s], y0);
        }
        #pragma unroll
        for (int s = 4; s < 8; s++) {
            h[s] = fmaf(h[s], dA[s], dtx * sBC[st][half * 8 + s]);
            y1   = fmaf(h[s], sBC[st][16 + half * 8 + s], y1);
        }
        float yacc = y0 + y1;
        yacc += __shfl_xor_sync(0xffffffffu, yacc, 1);
        if (half == 0) {
            float zv = sZ[st][dl];
            g_y[(rbase + st) * DI + d] =
                fmaf(xv, Dd, yacc) * (zv / (1.0f + __expf(-zv)));
        }
    }
}

// ------------------------------- launcher -------------------------------------
#define SMEM_NI4 (2 * (2 * 128 * 12 + 128 * 12) * 4)   // 36864
#define SMEM_NI2 (2 * (2 * 128 * 12 + 64 * 12) * 4)    // 30720
// TRANS epilogue needs 64*132*4 = 33792 <= SMEM_NI4, ok.

extern "C" void kernel_launch(void* const* d_in, const int* in_sizes, int n_in,
                              void* d_out, int out_size) {
    const float* bbox   = (const float*)d_in[0];
    const float* norm_w = (const float*)d_in[1];
    const float* norm_b = (const float*)d_in[2];
    const float* in_w   = (const float*)d_in[3];
    const float* conv_w = (const float*)d_in[4];
    const float* conv_b = (const float*)d_in[5];
    const float* xp_w   = (const float*)d_in[6];
    const float* dtp_w  = (const float*)d_in[7];
    const float* dtp_b  = (const float*)d_in[8];
    const float* A_log  = (const float*)d_in[9];
    const float* Dp     = (const float*)d_in[10];
    const float* out_w  = (const float*)d_in[11];
    float* out = (float*)d_out;

    cudaFuncSetAttribute(gemm_hf<4,0>, cudaFuncAttributeMaxDynamicSharedMemorySize, SMEM_NI4);
    cudaFuncSetAttribute(gemm_hf<4,1>, cudaFuncAttributeMaxDynamicSharedMemorySize, SMEM_NI4);
    cudaFuncSetAttribute(gemm_hf<2,0>, cudaFuncAttributeMaxDynamicSharedMemorySize, SMEM_NI2);

    float *xn, *xz, *xc, *yy, *xbuf, *xdp;
    cudaGetSymbolAddress((void**)&xn,   g_xn);
    cudaGetSymbolAddress((void**)&xz,   g_xz);
    cudaGetSymbolAddress((void**)&xc,   g_xc);
    cudaGetSymbolAddress((void**)&yy,   g_y);
    cudaGetSymbolAddress((void**)&xbuf, g_xbuf);
    cudaGetSymbolAddress((void**)&xdp,  g_xdp);

    for (int i = 0; i < 2; i++) {
        const float* xin = (i == 0) ? bbox : xbuf;
        float* xout      = (i == 0) ? xbuf : out;

        {   // layernorm
            dim3 g(49, 32);
            ln_kernel<<<g, 256>>>(xin, norm_w + i * CH, norm_b + i * CH, xn);
        }
        {   // in_proj: (25088,256)x(1024,256)^T -> f32 xz
            dim3 g(1024 / 128, MTOT / 128, 1);
            gemm_hf<4,0><<<g, 256, SMEM_NI4>>>(xn, in_w + (size_t)i * 2 * DI * CH, xz,
                                               MTOT, 2 * DI, CH);
        }
        // conv + silu
        conv_silu_kernel<<<(MTOT / 4) * (DI / 4) / 256, 256>>>(conv_w + i * DI * DCONV,
                                                               conv_b + i * DI);
        {   // x_proj: split-K=4 -> 4 partials (reduced inside scan loaders)
            dim3 g(1, MTOT / 128, 4);
            gemm_hf<2,0><<<g, 256, SMEM_NI2>>>(xc, xp_w + (size_t)i * 48 * DI, xdp,
                                               MTOT, 48, DI);
        }
        {   // chunked scan
            dim3 g1(B_SZ, DI / 64, NCH);
            scan_p1<<<g1, 128>>>(A_log + i * DI * DS,
                                 dtp_w + (size_t)i * DI * DTR, dtp_b + i * DI);
            scan_p2<<<(B_SZ * DI) / 128, 128>>>(A_log + i * DI * DS);
            scan_p3<<<g1, 128>>>(A_log + i * DI * DS, Dp + i * DI);
        }
        {   // out_proj: (25088,512)x(256,512)^T -> (B,256,L)
            dim3 g(256 / 128, MTOT / 128, 1);
            gemm_hf<4,1><<<g, 256, SMEM_NI4>>>(yy, out_w + (size_t)i * CH * DI, xout,
                                               MTOT, CH, DI);
        }
    }
}

// round 10
// speedup vs baseline: 2.5470x; 1.0006x over previous
#include <cuda_runtime.h>
#include <cuda_fp16.h>
#include <math.h>
#include <stdint.h>

#define B_SZ   32
#define CH     256
#define L_SEQ  784
#define DI     512
#define DS     16
#define DCONV  4
#define DTR    16
#define MTOT   (B_SZ * L_SEQ)   // 25088
#define NCH    16
#define CL     49               // 16 * 49 = 784

#define W_IN_OFF  0
#define W_XP_OFF  262144
#define W_OUT_OFF 286720
#define WTOT      417792

// ---------------- scratch (static __device__, no allocation) ----------------
__device__ __half g_xnh[(size_t)MTOT * CH];
__device__ __half g_xnl[(size_t)MTOT * CH];
__device__ __half g_xch[(size_t)MTOT * DI];
__device__ __half g_xcl[(size_t)MTOT * DI];
__device__ __half g_yh [(size_t)MTOT * DI];
__device__ __half g_yl [(size_t)MTOT * DI];
__device__ __half g_w16[2 * (size_t)WTOT];
__device__ float g_xz  [(size_t)MTOT * 2 * DI];
__device__ float g_xc  [(size_t)MTOT * DI];
__device__ float g_xdp [4][(size_t)MTOT * 48];
__device__ float g_xbuf[(size_t)B_SZ * CH * L_SEQ];
__device__ float g_dtv [(size_t)MTOT * DI];
__device__ float g_hloc[(size_t)B_SZ * NCH * DS * DI];
__device__ float g_hc0 [(size_t)B_SZ * NCH * DS * DI];
__device__ float g_sdt [(size_t)B_SZ * NCH * DI];

// ============================================================================
// helpers
// ============================================================================
__device__ __forceinline__ void split16(float x, __half& h, __half& l) {
    h = __float2half_rn(x);
    l = __float2half_rn(x - __half2float(h));
}
__device__ __forceinline__ void ldsm4(uint32_t q[4], uint32_t addr) {
    asm volatile("ldmatrix.sync.aligned.m8n8.x4.shared.b16 {%0,%1,%2,%3}, [%4];"
                 : "=r"(q[0]), "=r"(q[1]), "=r"(q[2]), "=r"(q[3]) : "r"(addr));
}
__device__ __forceinline__ void mma_f16(float* c, const uint32_t a[4],
                                        uint32_t b0, uint32_t b1) {
    asm volatile("mma.sync.aligned.m16n8k16.row.col.f32.f16.f16.f32 "
                 "{%0,%1,%2,%3},{%4,%5,%6,%7},{%8,%9},{%0,%1,%2,%3};"
                 : "+f"(c[0]), "+f"(c[1]), "+f"(c[2]), "+f"(c[3])
                 : "r"(a[0]), "r"(a[1]), "r"(a[2]), "r"(a[3]), "r"(b0), "r"(b1));
}

// ---------------- weight -> fp16 (single plane), both depths ------------------
__global__ void w16_kernel(const float* __restrict__ in_w,
                           const float* __restrict__ xp_w,
                           const float* __restrict__ out_w,
                           __half* __restrict__ w16) {
    int i = blockIdx.x * 256 + threadIdx.x;
    if (i >= 2 * WTOT) return;
    int depth = i / WTOT, r = i - depth * WTOT;
    float v;
    if (r < W_XP_OFF)       v = in_w [(size_t)depth * 262144 + r];
    else if (r < W_OUT_OFF) v = xp_w [(size_t)depth * 24576  + (r - W_XP_OFF)];
    else                    v = out_w[(size_t)depth * 131072 + (r - W_OUT_OFF)];
    w16[i] = __float2half_rn(v);
}

// ============================================================================
// GEMM C[M,N] = A[M,K]*B[N,K]^T ; A = pre-split fp16 hi/lo planes, B = fp16.
// 2-term mma (a_h*b + a_l*b). BM=128, BN=NI*32, BK=16, 256 thr,
// warps 2(m) x 4(n). Double buffered, 1 sync/k-tile. gridDim.z = split-K.
// Geometry/layout identical to R9; only the producer's data source changed.
// ============================================================================
template<int NI, int TRANS>
__global__ void __launch_bounds__(256)
gemm_hf(const __half* __restrict__ Ah, const __half* __restrict__ Al,
        const __half* __restrict__ Bw,
        float* __restrict__ C, int M, int N, int K) {
    constexpr int RS     = 12;              // u32 per smem row (16 f16 + pad)
    constexpr int A_U32  = 128 * RS;
    constexpr int BROWS  = NI * 32;
    constexpr int B_U32  = BROWS * RS;
    constexpr int STAGE  = 2 * A_U32 + B_U32;

    extern __shared__ uint32_t smu[];
    const uint32_t sb0 = (uint32_t)__cvta_generic_to_shared(smu);

    const int tid  = threadIdx.x;
    const int bm   = blockIdx.y * 128;
    const int bn   = blockIdx.x * BROWS;
    const int Kloc = K / gridDim.z;
    const int koff = blockIdx.z * Kloc;
    C += (size_t)blockIdx.z * M * N;

    const int warp = tid >> 5, lane = tid & 31;
    const int wm   = warp & 1, wn = warp >> 1;
    const int lm   = lane >> 3, lr = lane & 7;
    const int r    = lane >> 2, cc = lane & 3;

    const int pr = tid >> 1, ph = tid & 1;
    const int br2 = tid >> 2, bq2 = tid & 3;

    float acc[4][NI][4];
    #pragma unroll
    for (int i = 0; i < 4; i++)
        #pragma unroll
        for (int j = 0; j < NI; j++)
            #pragma unroll
            for (int v = 0; v < 4; v++) acc[i][j][v] = 0.0f;

    const int KT = Kloc >> 4;
    uint4 pAh, pAl, pB4;
    uint2 pB2;

    {
        size_t ao = (size_t)(bm + pr) * K + koff + ph * 8;
        pAh = *reinterpret_cast<const uint4*>(Ah + ao);
        pAl = *reinterpret_cast<const uint4*>(Al + ao);
        if (NI == 4) {
            int nb = min(bn + pr, N - 1);
            pB4 = *reinterpret_cast<const uint4*>(Bw + (size_t)nb * K + koff + ph * 8);
        } else {
            int nb = min(bn + br2, N - 1);
            pB2 = *reinterpret_cast<const uint2*>(Bw + (size_t)nb * K + koff + bq2 * 4);
        }
    }

    for (int kt = 0; kt < KT; kt++) {
        const int s = kt & 1;
        uint32_t* stg = smu + s * STAGE;

        // ---- producer: pure STS (data already split/packed in gmem) ----
        *reinterpret_cast<uint4*>(stg + pr * RS + ph * 4) = pAh;
        *reinterpret_cast<uint4*>(stg + A_U32 + pr * RS + ph * 4) = pAl;
        if (NI == 4)
            *reinterpret_cast<uint4*>(stg + 2 * A_U32 + pr * RS + ph * 4) = pB4;
        else
            *reinterpret_cast<uint2*>(stg + 2 * A_U32 + br2 * RS + bq2 * 2) = pB2;

        // ---- prefetch next tile ----
        if (kt + 1 < KT) {
            int k0 = koff + ((kt + 1) << 4);
            size_t ao = (size_t)(bm + pr) * K + k0 + ph * 8;
            pAh = *reinterpret_cast<const uint4*>(Ah + ao);
            pAl = *reinterpret_cast<const uint4*>(Al + ao);
            if (NI == 4) {
                int nb = min(bn + pr, N - 1);
                pB4 = *reinterpret_cast<const uint4*>(Bw + (size_t)nb * K + k0 + ph * 8);
            } else {
                int nb = min(bn + br2, N - 1);
                pB2 = *reinterpret_cast<const uint2*>(Bw + (size_t)nb * K + k0 + bq2 * 4);
            }
        }

        __syncthreads();

        // ---- consumer: LDSM + 2-term fp16 mma (unchanged from R9) ----
        {
            const uint32_t stb = sb0 + (uint32_t)(s * STAGE) * 4;
            uint32_t BH[NI][2];
            #pragma unroll
            for (int tt = 0; tt < NI / 2; tt++) {
                uint32_t rowb = wn * (NI * 8) + tt * 16 + (lm & 1) * 8 + lr;
                uint32_t ad = stb + (2 * A_U32) * 4 + rowb * 48 + (lm >> 1) * 16;
                uint32_t q[4];
                ldsm4(q, ad);
                BH[2*tt][0] = q[0]; BH[2*tt+1][0] = q[1];
                BH[2*tt][1] = q[2]; BH[2*tt+1][1] = q[3];
            }
            #pragma unroll
            for (int mi = 0; mi < 4; mi++) {
                uint32_t rowa = wm * 64 + mi * 16 + (lm & 1) * 8 + lr;
                uint32_t ad = stb + rowa * 48 + (lm >> 1) * 16;
                uint32_t AH[4], AL[4];
                ldsm4(AH, ad);
                ldsm4(AL, ad + A_U32 * 4);
                #pragma unroll
                for (int ni = 0; ni < NI; ni++) {
                    mma_f16(acc[mi][ni], AH, BH[ni][0], BH[ni][1]);
                    mma_f16(acc[mi][ni], AL, BH[ni][0], BH[ni][1]);
                }
            }
        }
    }

    if (!TRANS) {
        #pragma unroll
        for (int mi = 0; mi < 4; mi++) {
            int row0 = bm + wm * 64 + mi * 16 + r;
            #pragma unroll
            for (int ni = 0; ni < NI; ni++) {
                int col = bn + wn * (NI * 8) + ni * 8 + 2 * cc;
                if (col < N) {
                    *reinterpret_cast<float2*>(C + (size_t)row0 * N + col) =
                        make_float2(acc[mi][ni][0], acc[mi][ni][1]);
                    *reinterpret_cast<float2*>(C + (size_t)(row0 + 8) * N + col) =
                        make_float2(acc[mi][ni][2], acc[mi][ni][3]);
                }
            }
        }
    } else {
        float* ct = reinterpret_cast<float*>(smu);
        __syncthreads();
        #pragma unroll
        for (int half = 0; half < 2; half++) {
            if ((wn >> 1) == half) {
                #pragma unroll
                for (int mi = 0; mi < 4; mi++) {
                    int m0 = wm * 64 + mi * 16 + r;
                    #pragma unroll
                    for (int ni = 0; ni < NI; ni++) {
                        int n0 = (wn - half * 2) * (NI * 8) + ni * 8 + 2 * cc;
                        ct[(n0    ) * 132 + m0    ] = acc[mi][ni][0];
                        ct[(n0 + 1) * 132 + m0    ] = acc[mi][ni][1];
                        ct[(n0    ) * 132 + m0 + 8] = acc[mi][ni][2];
                        ct[(n0 + 1) * 132 + m0 + 8] = acc[mi][ni][3];
                    }
                }
            }
            __syncthreads();
            for (int i = tid; i < 64 * 128; i += 256) {
                int n = i >> 7, m = i & 127;
                int row = bm + m;
                int b = row / L_SEQ;
                int l = row - b * L_SEQ;
                C[((size_t)b * N + bn + half * 64 + n) * L_SEQ + l] = ct[n * 132 + m];
            }
            __syncthreads();
        }
    }
}

// ---------------- LayerNorm -> fp16 hi/lo planes, (B,C,L)->(B*L,C) ------------
__global__ void ln_kernel(const float* __restrict__ x,
                          const float* __restrict__ w,
                          const float* __restrict__ bb) {
    __shared__ float s[256][17];
    int l0 = blockIdx.x * 16;
    int b  = blockIdx.y;
    int tid = threadIdx.x;

    for (int i = tid; i < 256 * 16; i += 256) {
        int c = i >> 4, l = i & 15;
        s[c][l] = x[((size_t)b * CH + c) * L_SEQ + l0 + l];
    }
    __syncthreads();

    int l = tid >> 4, part = tid & 15;
    float a = 0.f, q = 0.f;
    #pragma unroll
    for (int j = 0; j < 16; j++) {
        float v = s[part + 16 * j][l];
        a += v;
        q = fmaf(v, v, q);
    }
    #pragma unroll
    for (int o = 1; o < 16; o <<= 1) {
        a += __shfl_xor_sync(0xffffffffu, a, o);
        q += __shfl_xor_sync(0xffffffffu, q, o);
    }
    float mu  = a * (1.0f / CH);
    float var = q * (1.0f / CH) - mu * mu;
    float inv = rsqrtf(var + 1e-5f);

    size_t base = (size_t)(b * L_SEQ + l0 + l) * CH;
    #pragma unroll
    for (int j = 0; j < 16; j++) {
        int c = part + 16 * j;
        float v = (s[c][l] - mu) * inv * w[c] + bb[c];
        __half h, lo;
        split16(v, h, lo);
        g_xnh[base + c] = h;
        g_xnl[base + c] = lo;
    }
}

// ---------------- causal conv (k=4) + SiLU -> f32 + fp16 hi/lo ----------------
__global__ void conv_silu_kernel(const float* __restrict__ cw,
                                 const float* __restrict__ cb) {
    int idx = blockIdx.x * 256 + threadIdx.x;
    int dq  = idx & 127;
    int d   = dq << 2;
    int blq = idx >> 7;
    int b   = blq / 196, lt = blq % 196;
    int l0  = lt * 4;
    size_t row0 = (size_t)b * L_SEQ + l0;

    float4 w0 = *reinterpret_cast<const float4*>(cw + (d + 0) * 4);
    float4 w1 = *reinterpret_cast<const float4*>(cw + (d + 1) * 4);
    float4 w2 = *reinterpret_cast<const float4*>(cw + (d + 2) * 4);
    float4 w3 = *reinterpret_cast<const float4*>(cw + (d + 3) * 4);
    const float wk[4][4] = {{w0.x, w1.x, w2.x, w3.x}, {w0.y, w1.y, w2.y, w3.y},
                            {w0.z, w1.z, w2.z, w3.z}, {w0.w, w1.w, w2.w, w3.w}};
    float4 bias4 = *reinterpret_cast<const float4*>(cb + d);

    float4 xx[7];
    #pragma unroll
    for (int k = 0; k < 7; k++) {
        int l = l0 - 3 + k;
        xx[k] = (l >= 0)
            ? *reinterpret_cast<const float4*>(g_xz + (row0 - 3 + k) * (2 * DI) + d)
            : make_float4(0.f, 0.f, 0.f, 0.f);
    }

    #pragma unroll
    for (int j = 0; j < 4; j++) {
        float4 acc = bias4;
        #pragma unroll
        for (int k = 0; k < 4; k++) {
            float4 v = xx[j + k];
            acc.x = fmaf(v.x, wk[k][0], acc.x);
            acc.y = fmaf(v.y, wk[k][1], acc.y);
            acc.z = fmaf(v.z, wk[k][2], acc.z);
            acc.w = fmaf(v.w, wk[k][3], acc.w);
        }
        float o[4] = {acc.x, acc.y, acc.z, acc.w};
        __half h[4], lo[4];
        #pragma unroll
        for (int k = 0; k < 4; k++) {
            o[k] = o[k] / (1.0f + __expf(-o[k]));
            split16(o[k], h[k], lo[k]);
        }
        size_t base = (row0 + j) * DI + d;
        *reinterpret_cast<float4*>(g_xc + base) = make_float4(o[0], o[1], o[2], o[3]);
        *reinterpret_cast<uint2*>(g_xch + base) = *reinterpret_cast<uint2*>(h);
        *reinterpret_cast<uint2*>(g_xcl + base) = *reinterpret_cast<uint2*>(lo);
    }
}

// ============================================================================
// Chunked selective scan (R7/R9, proven)
// ============================================================================
__device__ __forceinline__ void dA_build(float dtv, int half, bool powok,
                                         const float* a, float dA[8]) {
    if (powok) {
        float r1 = __expf(-dtv);
        float r2 = r1 * r1, r3 = r2 * r1, r4 = r2 * r2;
        dA[0] = r1; dA[1] = r2; dA[2] = r3; dA[3] = r4;
        dA[4] = r4 * r1; dA[5] = r4 * r2; dA[6] = r4 * r3; dA[7] = r4 * r4;
        if (half) {
            float r8 = r4 * r4;
            #pragma unroll
            for (int s = 0; s < 8; s++) dA[s] *= r8;
        }
    } else {
        #pragma unroll
        for (int s = 0; s < 8; s++) dA[s] = __expf(dtv * a[s]);
    }
}
__device__ __forceinline__ float xdp_sum(size_t ro) {
    return (g_xdp[0][ro] + g_xdp[1][ro]) + (g_xdp[2][ro] + g_xdp[3][ro]);
}

__global__ void __launch_bounds__(128)
scan_p1(const float* __restrict__ A_log,
        const float* __restrict__ dtw, const float* __restrict__ dtb) {
    int b  = blockIdx.x, gy = blockIdx.y, ch = blockIdx.z;
    int tid = threadIdx.x;
    int dl = tid >> 1, half = tid & 1;
    int d  = gy * 64 + dl, d0 = gy * 64;

    __shared__ float sR[CL][32];
    __shared__ float sX[CL][64];

    size_t rbase = (size_t)b * L_SEQ + ch * CL;
    for (int i = tid; i < CL * 32; i += 128) {
        int st = i >> 5, j = i & 31;
        sR[st][j] = xdp_sum((rbase + st) * 48 + j);
    }
    for (int i = tid; i < CL * 64; i += 128) {
        int st = i >> 6, j = i & 63;
        sX[st][j] = g_xc[(rbase + st) * DI + d0 + j];
    }
    __syncthreads();

    float w[DTR];
    #pragma unroll
    for (int i = 0; i < DTR; i++) w[i] = dtw[d * DTR + i];
    float bias = dtb[d];

    float a[8];
    bool powok = true;
    #pragma unroll
    for (int s = 0; s < 8; s++) {
        a[s] = -__expf(A_log[d * DS + half * 8 + s]);
        float kf = (float)(half * 8 + s + 1);
        powok = powok && (fabsf(-a[s] - kf) < 1e-3f * kf);
    }

    float h[8];
    #pragma unroll
    for (int s = 0; s < 8; s++) h[s] = 0.0f;
    float sumdt = 0.0f;

    for (int st = 0; st < CL; st++) {
        float s0 = 0.f, s1 = 0.f, s2 = 0.f, s3 = 0.f;
        #pragma unroll
        for (int i = 0; i < 4; i++) {
            s0 = fmaf(w[i],      sR[st][i],      s0);
            s1 = fmaf(w[4 + i],  sR[st][4 + i],  s1);
            s2 = fmaf(w[8 + i],  sR[st][8 + i],  s2);
            s3 = fmaf(w[12 + i], sR[st][12 + i], s3);
        }
        float dtl = bias + ((s0 + s1) + (s2 + s3));
        float dtv = (dtl > 20.0f) ? dtl : log1pf(__expf(dtl));
        if (half == 0) g_dtv[(rbase + st) * DI + d] = dtv;
        sumdt += dtv;
        float dtx = dtv * sX[st][dl];
        float dA[8];
        dA_build(dtv, half, powok, a, dA);
        #pragma unroll
        for (int s = 0; s < 8; s++)
            h[s] = fmaf(h[s], dA[s], dtx * sR[st][16 + half * 8 + s]);
    }
    size_t hb = (((size_t)b * NCH + ch) * DS + half * 8) * DI + d;
    #pragma unroll
    for (int s = 0; s < 8; s++) g_hloc[hb + (size_t)s * DI] = h[s];
    if (half == 0) g_sdt[((size_t)b * NCH + ch) * DI + d] = sumdt;
}

__global__ void __launch_bounds__(128)
scan_p2(const float* __restrict__ A_log) {
    int idx = blockIdx.x * 128 + threadIdx.x;
    int b = idx >> 9, d = idx & (DI - 1);

    float a[16];
    bool powok = true;
    #pragma unroll
    for (int s = 0; s < 16; s++) {
        a[s] = -__expf(A_log[d * DS + s]);
        float kf = (float)(s + 1);
        powok = powok && (fabsf(-a[s] - kf) < 1e-3f * kf);
    }
    float H[16];
    #pragma unroll
    for (int s = 0; s < 16; s++) H[s] = 0.0f;

    for (int c = 0; c < NCH; c++) {
        size_t hb = (((size_t)b * NCH + c) * DS) * DI + d;
        #pragma unroll
        for (int s = 0; s < 16; s++) g_hc0[hb + (size_t)s * DI] = H[s];
        float sdt = g_sdt[((size_t)b * NCH + c) * DI + d];
        float q[16];
        if (powok) {
            float r1 = __expf(-sdt);
            float r2 = r1 * r1, r3 = r2 * r1, r4 = r2 * r2;
            q[0]=r1; q[1]=r2; q[2]=r3; q[3]=r4;
            q[4]=r4*r1; q[5]=r4*r2; q[6]=r4*r3; q[7]=r4*r4;
            float r8 = r4 * r4;
            #pragma unroll
            for (int s = 0; s < 8; s++) q[8 + s] = q[s] * r8;
        } else {
            #pragma unroll
            for (int s = 0; s < 16; s++) q[s] = __expf(sdt * a[s]);
        }
        #pragma unroll
        for (int s = 0; s < 16; s++)
            H[s] = fmaf(H[s], q[s], g_hloc[hb + (size_t)s * DI]);
    }
}

__global__ void __launch_bounds__(128)
scan_p3(const float* __restrict__ A_log, const float* __restrict__ Dp) {
    int b  = blockIdx.x, gy = blockIdx.y, ch = blockIdx.z;
    int tid = threadIdx.x;
    int dl = tid >> 1, half = tid & 1;
    int d  = gy * 64 + dl, d0 = gy * 64;

    __shared__ float sBC[CL][32];
    __shared__ float sX[CL][64];
    __shared__ float sDT[CL][64];
    __shared__ float sZ[CL][64];

    size_t rbase = (size_t)b * L_SEQ + ch * CL;
    for (int i = tid; i < CL * 32; i += 128) {
        int st = i >> 5, j = i & 31;
        sBC[st][j] = xdp_sum((rbase + st) * 48 + 16 + j);
    }
    for (int i = tid; i < CL * 64; i += 128) {
        int st = i >> 6, j = i & 63;
        sX [st][j] = g_xc [(rbase + st) * DI + d0 + j];
        sDT[st][j] = g_dtv[(rbase + st) * DI + d0 + j];
        sZ [st][j] = g_xz [(rbase + st) * (2 * DI) + DI + d0 + j];
    }
    __syncthreads();

    float a[8];
    bool powok = true;
    #pragma unroll
    for (int s = 0; s < 8; s++) {
        a[s] = -__expf(A_log[d * DS + half * 8 + s]);
        float kf = (float)(half * 8 + s + 1);
        powok = powok && (fabsf(-a[s] - kf) < 1e-3f * kf);
    }
    float Dd = Dp[d];

    float h[8];
    size_t hb = (((size_t)b * NCH + ch) * DS + half * 8) * DI + d;
    #pragma unroll
    for (int s = 0; s < 8; s++) h[s] = g_hc0[hb + (size_t)s * DI];

    for (int st = 0; st < CL; st++) {
        float dtv = sDT[st][dl];
        float xv  = sX[st][dl];
        float dtx = dtv * xv;
        float dA[8];
        dA_build(dtv, half, powok, a, dA);
        float y0 = 0.f, y1 = 0.f;
        #pragma unroll
        for (int s = 0; s < 4; s++) {
            h[s] = fmaf(h[s], dA[s], dtx * sBC[st][half * 8 + s]);
            y0   = fmaf(h[s], sBC[st][16 + half * 8 + s], y0);
        }
        #pragma unroll
        for (int s = 4; s < 8; s++) {
            h[s] = fmaf(h[s], dA[s], dtx * sBC[st][half * 8 + s]);
            y1   = fmaf(h[s], sBC[st][16 + half * 8 + s], y1);
        }
        float yacc = y0 + y1;
        yacc += __shfl_xor_sync(0xffffffffu, yacc, 1);
        if (half == 0) {
            float zv = sZ[st][dl];
            float yf = fmaf(xv, Dd, yacc) * (zv / (1.0f + __expf(-zv)));
            __half hh, ll;
            split16(yf, hh, ll);
            g_yh[(rbase + st) * DI + d] = hh;
            g_yl[(rbase + st) * DI + d] = ll;
        }
    }
}

// ------------------------------- launcher -------------------------------------
#define SMEM_NI4 (2 * (2 * 128 * 12 + 128 * 12) * 4)   // 36864
#define SMEM_NI2 (2 * (2 * 128 * 12 + 64 * 12) * 4)    // 30720

extern "C" void kernel_launch(void* const* d_in, const int* in_sizes, int n_in,
                              void* d_out, int out_size) {
    const float* bbox   = (const float*)d_in[0];
    const float* norm_w = (const float*)d_in[1];
    const float* norm_b = (const float*)d_in[2];
    const float* in_w   = (const float*)d_in[3];
    const float* conv_w = (const float*)d_in[4];
    const float* conv_b = (const float*)d_in[5];
    const float* xp_w   = (const float*)d_in[6];
    const float* dtp_w  = (const float*)d_in[7];
    const float* dtp_b  = (const float*)d_in[8];
    const float* A_log  = (const float*)d_in[9];
    const float* Dp     = (const float*)d_in[10];
    const float* out_w  = (const float*)d_in[11];
    float* out = (float*)d_out;

    cudaFuncSetAttribute(gemm_hf<4,0>, cudaFuncAttributeMaxDynamicSharedMemorySize, SMEM_NI4);
    cudaFuncSetAttribute(gemm_hf<4,1>, cudaFuncAttributeMaxDynamicSharedMemorySize, SMEM_NI4);
    cudaFuncSetAttribute(gemm_hf<2,0>, cudaFuncAttributeMaxDynamicSharedMemorySize, SMEM_NI2);

    __half *xnh, *xnl, *xch, *xcl, *yh, *yl, *w16;
    float *xz, *xbuf, *xdp;
    cudaGetSymbolAddress((void**)&xnh, g_xnh);
    cudaGetSymbolAddress((void**)&xnl, g_xnl);
    cudaGetSymbolAddress((void**)&xch, g_xch);
    cudaGetSymbolAddress((void**)&xcl, g_xcl);
    cudaGetSymbolAddress((void**)&yh,  g_yh);
    cudaGetSymbolAddress((void**)&yl,  g_yl);
    cudaGetSymbolAddress((void**)&w16, g_w16);
    cudaGetSymbolAddress((void**)&xz,  g_xz);
    cudaGetSymbolAddress((void**)&xbuf, g_xbuf);
    cudaGetSymbolAddress((void**)&xdp,  g_xdp);

    // convert all weights to fp16 once per launch (both depths)
    w16_kernel<<<(2 * WTOT + 255) / 256, 256>>>(in_w, xp_w, out_w, w16);

    for (int i = 0; i < 2; i++) {
        const float* xin = (i == 0) ? bbox : xbuf;
        float* xout      = (i == 0) ? xbuf : out;
        size_t wb = (size_t)i * WTOT;

        {   // layernorm -> fp16 hi/lo planes
            dim3 g(49, 32);
            ln_kernel<<<g, 256>>>(xin, norm_w + i * CH, norm_b + i * CH);
        }
        {   // in_proj: (25088,256)x(1024,256)^T -> f32 xz
            dim3 g(1024 / 128, MTOT / 128, 1);
            gemm_hf<4,0><<<g, 256, SMEM_NI4>>>(xnh, xnl, w16 + wb + W_IN_OFF,
                                               xz, MTOT, 2 * DI, CH);
        }
        // conv + silu -> f32 + fp16 planes
        conv_silu_kernel<<<(MTOT / 4) * (DI / 4) / 256, 256>>>(conv_w + i * DI * DCONV,
                                                               conv_b + i * DI);
        {   // x_proj: split-K=4 -> 4 partials (reduced inside scan loaders)
            dim3 g(1, MTOT / 128, 4);
            gemm_hf<2,0><<<g, 256, SMEM_NI2>>>(xch, xcl, w16 + wb + W_XP_OFF,
                                               xdp, MTOT, 48, DI);
        }
        {   // chunked scan
            dim3 g1(B_SZ, DI / 64, NCH);
            scan_p1<<<g1, 128>>>(A_log + i * DI * DS,
                                 dtp_w + (size_t)i * DI * DTR, dtp_b + i * DI);
            scan_p2<<<(B_SZ * DI) / 128, 128>>>(A_log + i * DI * DS);
            scan_p3<<<g1, 128>>>(A_log + i * DI * DS, Dp + i * DI);
        }
        {   // out_proj: (25088,512)x(256,512)^T -> (B,256,L)
            dim3 g(256 / 128, MTOT / 128, 1);
            gemm_hf<4,1><<<g, 256, SMEM_NI4>>>(yh, yl, w16 + wb + W_OUT_OFF,
                                               xout, MTOT, CH, DI);
        }
    }
}